// round 7
// baseline (speedup 1.0000x reference)
#include <cuda_runtime.h>
#include <cuda.h>
#include <mma.h>
#include <cstdint>

using namespace nvcuda;

#define T_MAX 32768
#define H_DIM 1024
#define E_DIM 8

// tcgen05 is only legal in arch-accelerated (sm_10xa) compilation passes.
#if defined(__CUDA_ARCH_FEAT_SM103_ALL) || defined(__CUDA_ARCH_FEAT_SM100_ALL) || defined(__CUDA_ARCH_FEAT_SM101_ALL)
#define HAS_TCGEN05 1
#else
#define HAS_TCGEN05 0
#endif

// ---------------- scratch (no runtime allocations allowed) ----------------
__device__ int   g_best [T_MAX];
__device__ float g_bestp[T_MAX];
__device__ int   g_order[T_MAX];
#define NB_MAX (T_MAX / 256)
__device__ int g_hist[NB_MAX * E_DIM];
__device__ int g_boff[NB_MAX * E_DIM];
__device__ float g_A [T_MAX * H_DIM];   // gathered + RN-rounded-to-tf32 activations
__device__ float g_Wt[H_DIM * H_DIM];   // W_expert transposed ([N,K]) + RN tf32

// ---------------- generic helpers ----------------
__device__ __forceinline__ uint32_t smem_u32(const void* p) {
    uint32_t a;
    asm("{ .reg .u64 t; cvta.to.shared.u64 t, %1; cvt.u32.u64 %0, t; }" : "=r"(a) : "l"(p));
    return a;
}
__device__ __forceinline__ float round_tf32(float v) {
    uint32_t o;
    asm("cvt.rna.tf32.f32 %0, %1;" : "=r"(o) : "f"(v));
    return __uint_as_float(o);
}
__device__ __forceinline__ void cp16(uint32_t saddr, const void* g) {
    asm volatile("cp.async.cg.shared.global [%0], [%1], 16;\n" :: "r"(saddr), "l"(g));
}
__device__ __forceinline__ void cp_commit() { asm volatile("cp.async.commit_group;\n"); }
template <int N> __device__ __forceinline__ void cp_wait() {
    asm volatile("cp.async.wait_group %0;\n" :: "n"(N));
}

__device__ __forceinline__ uint32_t elect_one_pred() {
    uint32_t pred;
    asm volatile(
        "{\n\t.reg .pred p;\n\t"
        "elect.sync _|p, 0xFFFFFFFF;\n\t"
        "selp.b32 %0, 1, 0, p;\n\t}"
        : "=r"(pred));
    return pred;
}

// =====================================================================
// Kernel 1: router (UNCHANGED — fp32 order defines the permutation)
// =====================================================================
__global__ __launch_bounds__(256) void router_kernel(
    const float* __restrict__ x, const float* __restrict__ Wr,
    const float* __restrict__ br, int T)
{
    __shared__ float sW[E_DIM][H_DIM];
    for (int i = threadIdx.x; i < H_DIM * E_DIM; i += 256) {
        int h = i >> 3, e = i & 7;
        sW[e][h] = Wr[i];
    }
    __syncthreads();

    int warp = threadIdx.x >> 5;
    int lane = threadIdx.x & 31;
    int tokBase = blockIdx.x * 32 + warp * 4;

    for (int tt = 0; tt < 4; ++tt) {
        int t = tokBase + tt;
        if (t >= T) break;
        const float* xr = x + (size_t)t * H_DIM;

        float acc[E_DIM];
        #pragma unroll
        for (int e = 0; e < E_DIM; ++e) acc[e] = 0.f;
        #pragma unroll 4
        for (int i = 0; i < H_DIM / 32; ++i) {
            float xv = xr[i * 32 + lane];
            #pragma unroll
            for (int e = 0; e < E_DIM; ++e) acc[e] += xv * sW[e][i * 32 + lane];
        }
        #pragma unroll
        for (int e = 0; e < E_DIM; ++e) {
            #pragma unroll
            for (int off = 16; off; off >>= 1)
                acc[e] += __shfl_down_sync(0xffffffffu, acc[e], off);
        }
        if (lane == 0) {
            float l[E_DIM];
            #pragma unroll
            for (int e = 0; e < E_DIM; ++e) l[e] = acc[e] + br[e];
            int bi = 0; float bm = l[0];
            #pragma unroll
            for (int e = 1; e < E_DIM; ++e)
                if (l[e] > bm) { bm = l[e]; bi = e; }
            float s = 0.f;
            #pragma unroll
            for (int e = 0; e < E_DIM; ++e) s += expf(l[e] - bm);
            g_best [t] = bi;
            g_bestp[t] = 1.0f / s;
        }
    }
}

// =====================================================================
// Kernels 2-4: stable counting sort
// =====================================================================
__global__ void hist_kernel(int T)
{
    __shared__ int sh[E_DIM];
    if (threadIdx.x < E_DIM) sh[threadIdx.x] = 0;
    __syncthreads();
    int t = blockIdx.x * 256 + threadIdx.x;
    if (t < T) atomicAdd(&sh[g_best[t]], 1);
    __syncthreads();
    if (threadIdx.x < E_DIM)
        g_hist[blockIdx.x * E_DIM + threadIdx.x] = sh[threadIdx.x];
}

__global__ __launch_bounds__(256) void offsets_kernel(int NB)
{
    __shared__ int sh[NB_MAX * E_DIM];
    __shared__ int tot[E_DIM];
    __shared__ int base[E_DIM];
    const int tid = threadIdx.x;
    for (int i = tid; i < NB * E_DIM; i += 256) sh[i] = g_hist[i];
    __syncthreads();

    const int w = tid >> 5, l = tid & 31;
    if (w < E_DIM) {
        int run = 0;
        for (int c = 0; c < NB; c += 32) {
            int v = sh[(c + l) * E_DIM + w];
            int xs = v;
            #pragma unroll
            for (int off = 1; off < 32; off <<= 1) {
                int y = __shfl_up_sync(0xffffffffu, xs, off);
                if (l >= off) xs += y;
            }
            sh[(c + l) * E_DIM + w] = xs - v + run;
            run += __shfl_sync(0xffffffffu, xs, 31);
        }
        if (l == 0) tot[w] = run;
    }
    __syncthreads();
    if (tid == 0) {
        int b = 0;
        #pragma unroll
        for (int e = 0; e < E_DIM; ++e) { base[e] = b; b += tot[e]; }
    }
    __syncthreads();
    for (int i = tid; i < NB * E_DIM; i += 256)
        g_boff[i] = sh[i] + base[i & (E_DIM - 1)];
}

__global__ void scatter_kernel(int T)
{
    __shared__ int sb[256];
    int i = threadIdx.x;
    int t = blockIdx.x * 256 + i;
    sb[i] = (t < T) ? g_best[t] : -1;
    __syncthreads();
    if (t < T) {
        int e = sb[i];
        int rank = 0;
        for (int j = 0; j < i; ++j) rank += (sb[j] == e);
        int pos = g_boff[blockIdx.x * E_DIM + e] + rank;
        g_order[pos] = t;
    }
}

// =====================================================================
// Kernel 5: gather + RN-round to tf32
// =====================================================================
__global__ __launch_bounds__(256) void gather_round_kernel(const float* __restrict__ x)
{
    int t = blockIdx.x;
    int src = g_order[t];
    const float4* s = (const float4*)(x + (size_t)src * H_DIM);
    float4* d = (float4*)(g_A + (size_t)t * H_DIM);
    float4 v = s[threadIdx.x];
    v.x = round_tf32(v.x); v.y = round_tf32(v.y);
    v.z = round_tf32(v.z); v.w = round_tf32(v.w);
    d[threadIdx.x] = v;
}

// =====================================================================
// Kernel 6: transpose W_expert -> [N,K] with RN tf32 rounding
// =====================================================================
__global__ void transpose_round_kernel(const float* __restrict__ We)
{
    __shared__ float tile[32][33];
    int n = blockIdx.x * 32 + threadIdx.x;
    int k = blockIdx.y * 32 + threadIdx.y;
    tile[threadIdx.y][threadIdx.x] = round_tf32(We[(size_t)k * H_DIM + n]);
    __syncthreads();
    int on = blockIdx.x * 32 + threadIdx.y;
    int ok = blockIdx.y * 32 + threadIdx.x;
    g_Wt[(size_t)on * H_DIM + ok] = tile[threadIdx.x][threadIdx.y];
}

// =====================================================================
// tcgen05-only machinery
// =====================================================================
#if HAS_TCGEN05

#define MBARRIER_INIT(addr, cnt) \
    asm volatile("mbarrier.init.shared.b64 [%0], %1;" :: "r"((uint32_t)(addr)), "r"((uint32_t)(cnt)) : "memory")
#define MBARRIER_INVAL(addr) \
    asm volatile("mbarrier.inval.shared.b64 [%0];" :: "r"((uint32_t)(addr)) : "memory")
#define MBARRIER_EXPECT_TX(addr, bytes) \
    asm volatile("mbarrier.arrive.expect_tx.shared.b64 _, [%0], %1;" \
                 :: "r"((uint32_t)(addr)), "r"((uint32_t)(bytes)) : "memory")
#define MBARRIER_WAIT_PARITY(mbar, parity) do {                                   \
    asm volatile(                                                                 \
        "{\n\t.reg .pred P1;\n\t"                                                 \
        "WAIT_LOOP_%=:\n\t"                                                       \
        "mbarrier.try_wait.parity.acquire.cta.shared::cta.b64 P1, [%0], %1, 0x989680;\n\t" \
        "@P1 bra.uni WAIT_DONE_%=;\n\t"                                           \
        "bra.uni WAIT_LOOP_%=;\n\t"                                               \
        "WAIT_DONE_%=:\n\t}"                                                      \
        :: "r"((uint32_t)(mbar)), "r"((uint32_t)(parity)) : "memory");            \
} while (0)

#define CLUSTER_SYNC() do {                                              \
    asm volatile("barrier.cluster.arrive.aligned;" ::: "memory");        \
    asm volatile("barrier.cluster.wait.aligned;" ::: "memory");          \
} while (0)

#define TCGEN05_ALLOC(sres, n) \
    asm volatile("tcgen05.alloc.cta_group::1.sync.aligned.shared::cta.b32 [%0], %1;" \
                 :: "r"((uint32_t)(sres)), "r"((uint32_t)(n)) : "memory")
#define TCGEN05_DEALLOC(tm, n) \
    asm volatile("tcgen05.dealloc.cta_group::1.sync.aligned.b32 %0, %1;" :: "r"(tm), "r"((uint32_t)(n)))
#define TCGEN05_COMMIT(mbar) \
    asm volatile("tcgen05.commit.cta_group::1.mbarrier::arrive::one.shared::cluster.b64 [%0];" \
                 :: "r"((uint32_t)(mbar)) : "memory")
#define TCGEN05_COMMIT_MC(mbar, mask) \
    asm volatile("tcgen05.commit.cta_group::1.mbarrier::arrive::one.shared::cluster.multicast::cluster.b64 [%0], %1;" \
                 :: "r"((uint32_t)(mbar)), "h"((uint16_t)(mask)) : "memory")
#define TCGEN05_FENCE_AFTER()  asm volatile("tcgen05.fence::after_thread_sync;" ::: "memory")
#define TCGEN05_FENCE_BEFORE() asm volatile("tcgen05.fence::before_thread_sync;" ::: "memory")
#define TCGEN05_WAIT_LD()      asm volatile("tcgen05.wait::ld.sync.aligned;" ::: "memory")

#define TMA_LOAD_2D(smem_addr, tmap, cx, cy, mbar)                                \
    asm volatile(                                                                 \
        "cp.async.bulk.tensor.2d.shared::cta.global.tile.mbarrier::complete_tx::bytes " \
        "[%0], [%1, {%2, %3}], [%4];"                                             \
        :: "r"((uint32_t)(smem_addr)), "l"(tmap), "r"((int32_t)(cx)),             \
           "r"((int32_t)(cy)), "r"((uint32_t)(mbar)) : "memory")

#define TMA_LOAD_2D_MC(smem_addr, tmap, cx, cy, mbar, mask)                       \
    asm volatile(                                                                 \
        "cp.async.bulk.tensor.2d.shared::cluster.global.tile.mbarrier::complete_tx::bytes.multicast::cluster " \
        "[%0], [%1, {%2, %3}], [%4], %5;"                                         \
        :: "r"((uint32_t)(smem_addr)), "l"(tmap), "r"((int32_t)(cx)),             \
           "r"((int32_t)(cy)), "r"((uint32_t)(mbar)), "h"((uint16_t)(mask)) : "memory")

#define TCGEN05_LD_32X32B_X32(r, tmem_addr)                                     \
    asm volatile(                                                               \
        "tcgen05.ld.sync.aligned.32x32b.x32.b32 "                               \
        "{%0, %1, %2, %3, %4, %5, %6, %7, "                                     \
        " %8, %9, %10, %11, %12, %13, %14, %15, "                               \
        " %16, %17, %18, %19, %20, %21, %22, %23, "                             \
        " %24, %25, %26, %27, %28, %29, %30, %31}, [%32];"                      \
        : "=r"((r)[0]),  "=r"((r)[1]),  "=r"((r)[2]),  "=r"((r)[3]),            \
          "=r"((r)[4]),  "=r"((r)[5]),  "=r"((r)[6]),  "=r"((r)[7]),            \
          "=r"((r)[8]),  "=r"((r)[9]),  "=r"((r)[10]), "=r"((r)[11]),           \
          "=r"((r)[12]), "=r"((r)[13]), "=r"((r)[14]), "=r"((r)[15]),           \
          "=r"((r)[16]), "=r"((r)[17]), "=r"((r)[18]), "=r"((r)[19]),           \
          "=r"((r)[20]), "=r"((r)[21]), "=r"((r)[22]), "=r"((r)[23]),           \
          "=r"((r)[24]), "=r"((r)[25]), "=r"((r)[26]), "=r"((r)[27]),           \
          "=r"((r)[28]), "=r"((r)[29]), "=r"((r)[30]), "=r"((r)[31])            \
        : "r"(tmem_addr))

static constexpr uint64_t SMEM_DESC_BASE_SW128 =
    (uint64_t(2)  << 61) | (uint64_t(1) << 46) | (uint64_t(64) << 32) | (uint64_t(1) << 16);
#define MAKE_SMEM_DESC(base) (SMEM_DESC_BASE_SW128 | ((uint64_t)((base) >> 4) & 0x3FFF))

// idesc kind::tf32 SS cg1: d=F32(1<<4), a=TF32(2<<7), b=TF32(2<<10),
// (N=256/8)<<17, (M=128/16)<<24.
#define GEMM_IDESC 0x8400910u

__device__ __forceinline__ void mma_tf32_ss(uint32_t d, uint64_t a, uint64_t b, uint32_t en) {
    asm volatile(
        "{\n\t.reg .pred p;\n\t"
        "setp.ne.u32 p, %4, 0;\n\t"
        "tcgen05.mma.cta_group::1.kind::tf32 [%0], %1, %2, %3, {%5, %5, %5, %5}, p;\n\t}"
        :: "r"(d), "l"(a), "l"(b), "r"(GEMM_IDESC), "r"(en), "r"(0u) : "memory");
}
#endif  // HAS_TCGEN05

// =====================================================================
// Kernel 7a: tcgen05 tf32 GEMM 256x256, TMA + warp specialization +
// cluster-4 cooperative-slice A multicast (A L2 traffic /4).
// =====================================================================
#define GBM 256
#define GBN 256
#define GBK 32
#define CLUSTER_X 4
#define A_STAGE (GBM * GBK * 4)            // 32768 B
#define A_SLICE (A_STAGE / CLUSTER_X)      // 8192 B (64 rows)
#define B_STAGE (GBN * GBK * 4)            // 32768 B
#define STAGE_BYTES (A_STAGE + B_STAGE)    // 65536 B
#define NSTAGES 3
#define GEMM_SMEM (4096 + NSTAGES * STAGE_BYTES)
#define MC_MASK 0xF

// mbar smem offsets (from sb):
#define MB_FULL(s)  (sb + 8  + (s) * 16)
#define MB_EMPTY(s) (sb + 64 + (s) * 16)
#define MB_DONE     (sb + 120)

__global__ __launch_bounds__(256)
#if HAS_TCGEN05
__cluster_dims__(CLUSTER_X, 1, 1)
#endif
void gemm_tc_kernel(const __grid_constant__ CUtensorMap tmA,
                    const __grid_constant__ CUtensorMap tmB,
                    const float* __restrict__ be, float* __restrict__ out)
{
#if HAS_TCGEN05
    extern __shared__ char smem[];
    uint32_t sb = smem_u32(smem);
    const int tid  = threadIdx.x;
    const int wid  = tid >> 5;
    const int lane = tid & 31;
    const int rowBase = blockIdx.y * GBM;
    const int colBase = blockIdx.x * GBN;
    uint32_t rank;
    asm("mov.u32 %0, %%cluster_ctarank;" : "=r"(rank));

    float* sBias = (float*)(smem + 128);     // 256 f32
    float* sBp   = (float*)(smem + 1152);    // 256 f32
    const uint32_t buf0 = (sb + 2176 + 1023) & ~1023u;

    if (wid == 0) TCGEN05_ALLOC(sb + 0, 512);
    if (tid == 0) {
        #pragma unroll
        for (int s = 0; s < NSTAGES; ++s) {
            MBARRIER_INIT(MB_FULL(s), 1);
            MBARRIER_INIT(MB_EMPTY(s), CLUSTER_X);   // 4 multicast commits
        }
        MBARRIER_INIT(MB_DONE, 1);
    }
    sBias[tid] = be[colBase + tid];
    sBp[tid]   = g_bestp[rowBase + tid];
    __syncthreads();
    // all cluster CTAs' mbarriers must be live before any multicast targets them
    CLUSTER_SYNC();
    uint32_t tmem;
    asm volatile("ld.shared.b32 %0, [%1];" : "=r"(tmem) : "r"(sb + 0));

    const int NST = H_DIM / GBK;   // 32

    if (wid == 1 && elect_one_pred()) {
        // ------- TMA producer: own A slice multicast to cluster + own B -------
        int ph[NSTAGES] = {1, 1, 1};
        for (int kt = 0; kt < NST; ++kt) {
            const int s = kt % NSTAGES;
            MBARRIER_WAIT_PARITY(MB_EMPTY(s), ph[s]); ph[s] ^= 1;
            const uint32_t ab = buf0 + s * STAGE_BYTES;
            MBARRIER_EXPECT_TX(MB_FULL(s), STAGE_BYTES);
            TMA_LOAD_2D_MC(ab + rank * A_SLICE, &tmA,
                           kt * GBK, rowBase + (int)rank * 64,
                           MB_FULL(s), MC_MASK);
            TMA_LOAD_2D(ab + A_STAGE, &tmB, kt * GBK, colBase, MB_FULL(s));
        }
    }
    if (wid == 0 && elect_one_pred()) {
        // ------- MMA consumer; buffer release is cluster-wide -------
        int ph[NSTAGES] = {0, 0, 0};
        for (int kt = 0; kt < NST; ++kt) {
            const int s = kt % NSTAGES;
            MBARRIER_WAIT_PARITY(MB_FULL(s), ph[s]); ph[s] ^= 1;
            const uint32_t ab = buf0 + s * STAGE_BYTES;
            uint64_t ad0 = MAKE_SMEM_DESC(ab);
            uint64_t ad1 = MAKE_SMEM_DESC(ab + 128 * 128);   // rows 128..255
            uint64_t bd  = MAKE_SMEM_DESC(ab + A_STAGE);
            #pragma unroll
            for (int ks = 0; ks < 4; ++ks) {
                uint32_t en = (kt | ks) != 0;
                mma_tf32_ss(tmem,       ad0 + ks * 2, bd + ks * 2, en);
                mma_tf32_ss(tmem + 256, ad1 + ks * 2, bd + ks * 2, en);
            }
            TCGEN05_COMMIT_MC(MB_EMPTY(s), MC_MASK);  // release in ALL cluster CTAs
        }
        TCGEN05_COMMIT(MB_DONE);
    }

    MBARRIER_WAIT_PARITY(MB_DONE, 0);
    TCGEN05_FENCE_AFTER();

    {
        const int half   = wid >> 2;
        const int rowLoc = half * 128 + (wid & 3) * 32 + lane;
        const float p = sBp[rowLoc];
        const uint32_t dbase = tmem + half * 256;
        float* orow = out + (size_t)(rowBase + rowLoc) * H_DIM + colBase;
        #pragma unroll
        for (int ch = 0; ch < 8; ++ch) {
            uint32_t r[32];
            TCGEN05_LD_32X32B_X32(r, dbase + ch * 32);
            TCGEN05_WAIT_LD();
            #pragma unroll
            for (int i = 0; i < 32; i += 4) {
                float4 v;
                v.x = (__uint_as_float(r[i + 0]) + sBias[ch * 32 + i + 0]) * p;
                v.y = (__uint_as_float(r[i + 1]) + sBias[ch * 32 + i + 1]) * p;
                v.z = (__uint_as_float(r[i + 2]) + sBias[ch * 32 + i + 2]) * p;
                v.w = (__uint_as_float(r[i + 3]) + sBias[ch * 32 + i + 3]) * p;
                *(float4*)(orow + ch * 32 + i) = v;
            }
        }
        TCGEN05_FENCE_BEFORE();
    }
    __syncthreads();
    // peers' multicast commits/loads must all have landed before teardown
    CLUSTER_SYNC();
    if (tid == 0) {
        #pragma unroll
        for (int s = 0; s < NSTAGES; ++s) {
            MBARRIER_INVAL(MB_FULL(s));
            MBARRIER_INVAL(MB_EMPTY(s));
        }
        MBARRIER_INVAL(MB_DONE);
    }
    __syncthreads();
    if (wid == 0) TCGEN05_DEALLOC(tmem, 512);
    CLUSTER_SYNC();
#endif  // HAS_TCGEN05
}

// =====================================================================
// Kernel 7b: WMMA tf32 fallback 128x128 (compiled in ALL passes)
// =====================================================================
#define FBM 128
#define FBN 128
#define FBK 16
#define FLD 20
#define FNKT (H_DIM / FBK)
#define FB_SMEM (( (2*FBM*FLD) + (2*FBN*FLD) + 8*256 + FBM + FBN ) * 4)

__global__ __launch_bounds__(256) void gemm_wmma_kernel(
    const float* __restrict__ be, float* __restrict__ out)
{
    extern __shared__ float fsm[];
    float* As    = fsm;
    float* Bs    = As + 2 * FBM * FLD;
    float* sC    = Bs + 2 * FBN * FLD;
    float* sBias = sC + 8 * 256;
    float* sBp   = sBias + FBN;

    const int tid = threadIdx.x;
    const int rowBase = blockIdx.y * FBM;
    const int colBase = blockIdx.x * FBN;

    if (tid < FBM)       sBp[tid]         = g_bestp[rowBase + tid];
    else                 sBias[tid - FBM] = be[colBase + tid - FBM];

    const int arow = tid >> 1;
    const int aseg = (tid & 1) * 8;
    const float* aSrc = g_A  + (size_t)(rowBase + arow) * H_DIM + aseg;
    const float* bSrc = g_Wt + (size_t)(colBase + arow) * H_DIM + aseg;
    const uint32_t asm_base = smem_u32(As);
    const uint32_t bsm_base = smem_u32(Bs);

    auto load_tiles = [&](int buf, int kt) {
        const int k0 = kt * FBK;
        uint32_t ao = asm_base + (buf * FBM * FLD + arow * FLD + aseg) * 4;
        uint32_t bo = bsm_base + (buf * FBN * FLD + arow * FLD + aseg) * 4;
        cp16(ao,      aSrc + k0);
        cp16(ao + 16, aSrc + k0 + 4);
        cp16(bo,      bSrc + k0);
        cp16(bo + 16, bSrc + k0 + 4);
    };

    const int warpId = tid >> 5;
    const int wm = warpId >> 2;
    const int wn = warpId & 3;

    wmma::fragment<wmma::accumulator, 16, 16, 8, float> acc[4][2];
    #pragma unroll
    for (int mi = 0; mi < 4; ++mi)
        #pragma unroll
        for (int ni = 0; ni < 2; ++ni)
            wmma::fill_fragment(acc[mi][ni], 0.0f);

    load_tiles(0, 0);
    cp_commit();

    for (int kt = 0; kt < FNKT; ++kt) {
        if (kt + 1 < FNKT) {
            load_tiles((kt + 1) & 1, kt + 1);
            cp_commit();
            cp_wait<1>();
        } else {
            cp_wait<0>();
        }
        __syncthreads();

        const int buf = kt & 1;
        #pragma unroll
        for (int ks = 0; ks < 2; ++ks) {
            wmma::fragment<wmma::matrix_a, 16, 16, 8, wmma::precision::tf32,
                           wmma::row_major> af[4];
            wmma::fragment<wmma::matrix_b, 16, 16, 8, wmma::precision::tf32,
                           wmma::col_major> bf[2];
            #pragma unroll
            for (int mi = 0; mi < 4; ++mi)
                wmma::load_matrix_sync(
                    af[mi], &As[buf * FBM * FLD + (wm * 64 + mi * 16) * FLD + ks * 8], FLD);
            #pragma unroll
            for (int ni = 0; ni < 2; ++ni)
                wmma::load_matrix_sync(
                    bf[ni], &Bs[buf * FBN * FLD + (wn * 32 + ni * 16) * FLD + ks * 8], FLD);
            #pragma unroll
            for (int mi = 0; mi < 4; ++mi)
                #pragma unroll
                for (int ni = 0; ni < 2; ++ni)
                    wmma::mma_sync(acc[mi][ni], af[mi], bf[ni], acc[mi][ni]);
        }
        __syncthreads();
    }

    const int lane = tid & 31;
    float* stg = &sC[warpId * 256];
    #pragma unroll
    for (int mi = 0; mi < 4; ++mi) {
        #pragma unroll
        for (int ni = 0; ni < 2; ++ni) {
            wmma::store_matrix_sync(stg, acc[mi][ni], 16, wmma::mem_row_major);
            __syncwarp();
            const int r = lane >> 1;
            const int c = (lane & 1) * 8;
            const int rowL = wm * 64 + mi * 16 + r;
            const int colL = wn * 32 + ni * 16 + c;
            const float p = sBp[rowL];
            float4 v0 = *(const float4*)&stg[r * 16 + c];
            float4 v1 = *(const float4*)&stg[r * 16 + c + 4];
            float4 o0, o1;
            o0.x = (v0.x + sBias[colL + 0]) * p;
            o0.y = (v0.y + sBias[colL + 1]) * p;
            o0.z = (v0.z + sBias[colL + 2]) * p;
            o0.w = (v0.w + sBias[colL + 3]) * p;
            o1.x = (v1.x + sBias[colL + 4]) * p;
            o1.y = (v1.y + sBias[colL + 5]) * p;
            o1.z = (v1.z + sBias[colL + 6]) * p;
            o1.w = (v1.w + sBias[colL + 7]) * p;
            float* dst = out + (size_t)(rowBase + rowL) * H_DIM + colBase + colL;
            *(float4*)(dst + 0) = o0;
            *(float4*)(dst + 4) = o1;
            __syncwarp();
        }
    }
}

// =====================================================================
// host: tensor-map construction via driver entry point (no -lcuda link)
// =====================================================================
typedef CUresult (*PFN_encodeTiled)(
    CUtensorMap*, CUtensorMapDataType, cuuint32_t, void*,
    const cuuint64_t*, const cuuint64_t*, const cuuint32_t*, const cuuint32_t*,
    CUtensorMapInterleave, CUtensorMapSwizzle, CUtensorMapL2promotion,
    CUtensorMapFloatOOBfill);

static PFN_encodeTiled get_encode_fn()
{
    void* fn = nullptr;
    cudaDriverEntryPointQueryResult qres = cudaDriverEntryPointSymbolNotFound;
#if CUDART_VERSION >= 12050
    cudaGetDriverEntryPointByVersion("cuTensorMapEncodeTiled", &fn, 12000,
                                     cudaEnableDefault, &qres);
#else
    cudaGetDriverEntryPoint("cuTensorMapEncodeTiled", &fn,
                            cudaEnableDefault, &qres);
#endif
    if (qres != cudaDriverEntryPointSuccess) return nullptr;
    return (PFN_encodeTiled)fn;
}

static bool make_map(PFN_encodeTiled enc, CUtensorMap* tm, void* base,
                     uint64_t d0, uint64_t d1, uint32_t b0, uint32_t b1)
{
    cuuint64_t dims[2]    = {d0, d1};
    cuuint64_t strides[1] = {d0 * 4};
    cuuint32_t box[2]     = {b0, b1};
    cuuint32_t es[2]      = {1, 1};
    CUresult r = enc(tm, CU_TENSOR_MAP_DATA_TYPE_FLOAT32, 2, base,
                     dims, strides, box, es,
                     CU_TENSOR_MAP_INTERLEAVE_NONE, CU_TENSOR_MAP_SWIZZLE_128B,
                     CU_TENSOR_MAP_L2_PROMOTION_L2_128B,
                     CU_TENSOR_MAP_FLOAT_OOB_FILL_NONE);
    return r == CUDA_SUCCESS;
}

// =====================================================================
// launch
// =====================================================================
extern "C" void kernel_launch(void* const* d_in, const int* in_sizes, int n_in,
                              void* d_out, int out_size)
{
    const float* x  = (const float*)d_in[0];
    const float* Wr = (const float*)d_in[1];
    const float* br = (const float*)d_in[2];
    const float* We = (const float*)d_in[3];
    const float* be = (const float*)d_in[4];
    float* out = (float*)d_out;

    const int T  = in_sizes[0] / H_DIM;   // 32768
    const int NB = T / 256;

    router_kernel<<<T / 32, 256>>>(x, Wr, br, T);
    transpose_round_kernel<<<dim3(H_DIM / 32, H_DIM / 32), dim3(32, 32)>>>(We);
    hist_kernel<<<NB, 256>>>(T);
    offsets_kernel<<<1, 256>>>(NB);
    scatter_kernel<<<NB, 256>>>(T);
    gather_round_kernel<<<T, 256>>>(x);

    // which GEMM variant is live in this binary?
    cudaFuncAttributes attr;
    attr.numRegs = 0;
    cudaFuncGetAttributes(&attr, (const void*)gemm_tc_kernel);

    bool tc_ok = (attr.numRegs > 32);
    CUtensorMap tmA, tmB;
    if (tc_ok) {
        PFN_encodeTiled enc = get_encode_fn();
        void *pA = nullptr, *pW = nullptr;
        tc_ok = enc != nullptr
             && cudaGetSymbolAddress(&pA, g_A)  == cudaSuccess
             && cudaGetSymbolAddress(&pW, g_Wt) == cudaSuccess
             && make_map(enc, &tmA, pA, H_DIM, (uint64_t)T, GBK, 64)    // A slice box: 32x64
             && make_map(enc, &tmB, pW, H_DIM, H_DIM,       GBK, GBN);  // B box: 32x256
    }

    if (tc_ok) {
        cudaFuncSetAttribute(gemm_tc_kernel,
                             cudaFuncAttributeMaxDynamicSharedMemorySize, GEMM_SMEM);
        dim3 gtc(H_DIM / GBN, T / GBM);   // (4, 128); x is the cluster dim
        gemm_tc_kernel<<<gtc, 256, GEMM_SMEM>>>(tmA, tmB, be, out);
    } else {
        cudaFuncSetAttribute(gemm_wmma_kernel,
                             cudaFuncAttributeMaxDynamicSharedMemorySize, FB_SMEM);
        dim3 gfb(H_DIM / FBN, T / FBM);   // (8, 256)
        gemm_wmma_kernel<<<gfb, 256, FB_SMEM>>>(be, out);
    }
}

// round 8
// speedup vs baseline: 1.0735x; 1.0735x over previous
#include <cuda_runtime.h>
#include <cuda.h>
#include <mma.h>
#include <cstdint>

using namespace nvcuda;

#define T_MAX 32768
#define H_DIM 1024
#define E_DIM 8

// tcgen05 is only legal in arch-accelerated (sm_10xa) compilation passes.
#if defined(__CUDA_ARCH_FEAT_SM103_ALL) || defined(__CUDA_ARCH_FEAT_SM100_ALL) || defined(__CUDA_ARCH_FEAT_SM101_ALL)
#define HAS_TCGEN05 1
#else
#define HAS_TCGEN05 0
#endif

// ---------------- scratch (no runtime allocations allowed) ----------------
__device__ int   g_best [T_MAX];
__device__ float g_bestp[T_MAX];
__device__ int   g_order[T_MAX];
#define NB_MAX (T_MAX / 256)
__device__ int g_hist[NB_MAX * E_DIM];
__device__ int g_boff[NB_MAX * E_DIM];
__device__ float g_A [T_MAX * H_DIM];   // gathered + RN-rounded-to-tf32 activations
__device__ float g_Wt[H_DIM * H_DIM];   // W_expert transposed ([N,K]) + RN tf32

// ---------------- generic helpers ----------------
__device__ __forceinline__ uint32_t smem_u32(const void* p) {
    uint32_t a;
    asm("{ .reg .u64 t; cvta.to.shared.u64 t, %1; cvt.u32.u64 %0, t; }" : "=r"(a) : "l"(p));
    return a;
}
__device__ __forceinline__ float round_tf32(float v) {
    uint32_t o;
    asm("cvt.rna.tf32.f32 %0, %1;" : "=r"(o) : "f"(v));
    return __uint_as_float(o);
}
__device__ __forceinline__ void cp16(uint32_t saddr, const void* g) {
    asm volatile("cp.async.cg.shared.global [%0], [%1], 16;\n" :: "r"(saddr), "l"(g));
}
__device__ __forceinline__ void cp_commit() { asm volatile("cp.async.commit_group;\n"); }
template <int N> __device__ __forceinline__ void cp_wait() {
    asm volatile("cp.async.wait_group %0;\n" :: "n"(N));
}

__device__ __forceinline__ uint32_t elect_one_pred() {
    uint32_t pred;
    asm volatile(
        "{\n\t.reg .pred p;\n\t"
        "elect.sync _|p, 0xFFFFFFFF;\n\t"
        "selp.b32 %0, 1, 0, p;\n\t}"
        : "=r"(pred));
    return pred;
}

// =====================================================================
// Kernel 1: router (UNCHANGED — fp32 order defines the permutation)
// =====================================================================
__global__ __launch_bounds__(256) void router_kernel(
    const float* __restrict__ x, const float* __restrict__ Wr,
    const float* __restrict__ br, int T)
{
    __shared__ float sW[E_DIM][H_DIM];
    for (int i = threadIdx.x; i < H_DIM * E_DIM; i += 256) {
        int h = i >> 3, e = i & 7;
        sW[e][h] = Wr[i];
    }
    __syncthreads();

    int warp = threadIdx.x >> 5;
    int lane = threadIdx.x & 31;
    int tokBase = blockIdx.x * 32 + warp * 4;

    for (int tt = 0; tt < 4; ++tt) {
        int t = tokBase + tt;
        if (t >= T) break;
        const float* xr = x + (size_t)t * H_DIM;

        float acc[E_DIM];
        #pragma unroll
        for (int e = 0; e < E_DIM; ++e) acc[e] = 0.f;
        #pragma unroll 4
        for (int i = 0; i < H_DIM / 32; ++i) {
            float xv = xr[i * 32 + lane];
            #pragma unroll
            for (int e = 0; e < E_DIM; ++e) acc[e] += xv * sW[e][i * 32 + lane];
        }
        #pragma unroll
        for (int e = 0; e < E_DIM; ++e) {
            #pragma unroll
            for (int off = 16; off; off >>= 1)
                acc[e] += __shfl_down_sync(0xffffffffu, acc[e], off);
        }
        if (lane == 0) {
            float l[E_DIM];
            #pragma unroll
            for (int e = 0; e < E_DIM; ++e) l[e] = acc[e] + br[e];
            int bi = 0; float bm = l[0];
            #pragma unroll
            for (int e = 1; e < E_DIM; ++e)
                if (l[e] > bm) { bm = l[e]; bi = e; }
            float s = 0.f;
            #pragma unroll
            for (int e = 0; e < E_DIM; ++e) s += expf(l[e] - bm);
            g_best [t] = bi;
            g_bestp[t] = 1.0f / s;
        }
    }
}

// =====================================================================
// Kernels 2-4: stable counting sort
// =====================================================================
__global__ void hist_kernel(int T)
{
    __shared__ int sh[E_DIM];
    if (threadIdx.x < E_DIM) sh[threadIdx.x] = 0;
    __syncthreads();
    int t = blockIdx.x * 256 + threadIdx.x;
    if (t < T) atomicAdd(&sh[g_best[t]], 1);
    __syncthreads();
    if (threadIdx.x < E_DIM)
        g_hist[blockIdx.x * E_DIM + threadIdx.x] = sh[threadIdx.x];
}

__global__ __launch_bounds__(256) void offsets_kernel(int NB)
{
    __shared__ int sh[NB_MAX * E_DIM];
    __shared__ int tot[E_DIM];
    __shared__ int base[E_DIM];
    const int tid = threadIdx.x;
    for (int i = tid; i < NB * E_DIM; i += 256) sh[i] = g_hist[i];
    __syncthreads();

    const int w = tid >> 5, l = tid & 31;
    if (w < E_DIM) {
        int run = 0;
        for (int c = 0; c < NB; c += 32) {
            int v = sh[(c + l) * E_DIM + w];
            int xs = v;
            #pragma unroll
            for (int off = 1; off < 32; off <<= 1) {
                int y = __shfl_up_sync(0xffffffffu, xs, off);
                if (l >= off) xs += y;
            }
            sh[(c + l) * E_DIM + w] = xs - v + run;
            run += __shfl_sync(0xffffffffu, xs, 31);
        }
        if (l == 0) tot[w] = run;
    }
    __syncthreads();
    if (tid == 0) {
        int b = 0;
        #pragma unroll
        for (int e = 0; e < E_DIM; ++e) { base[e] = b; b += tot[e]; }
    }
    __syncthreads();
    for (int i = tid; i < NB * E_DIM; i += 256)
        g_boff[i] = sh[i] + base[i & (E_DIM - 1)];
}

__global__ void scatter_kernel(int T)
{
    __shared__ int sb[256];
    int i = threadIdx.x;
    int t = blockIdx.x * 256 + i;
    sb[i] = (t < T) ? g_best[t] : -1;
    __syncthreads();
    if (t < T) {
        int e = sb[i];
        int rank = 0;
        for (int j = 0; j < i; ++j) rank += (sb[j] == e);
        int pos = g_boff[blockIdx.x * E_DIM + e] + rank;
        g_order[pos] = t;
    }
}

// =====================================================================
// Kernel 5: gather + RN-round to tf32
// =====================================================================
__global__ __launch_bounds__(256) void gather_round_kernel(const float* __restrict__ x)
{
    int t = blockIdx.x;
    int src = g_order[t];
    const float4* s = (const float4*)(x + (size_t)src * H_DIM);
    float4* d = (float4*)(g_A + (size_t)t * H_DIM);
    float4 v = s[threadIdx.x];
    v.x = round_tf32(v.x); v.y = round_tf32(v.y);
    v.z = round_tf32(v.z); v.w = round_tf32(v.w);
    d[threadIdx.x] = v;
}

// =====================================================================
// Kernel 6: transpose W_expert -> [N,K] with RN tf32 rounding
// =====================================================================
__global__ void transpose_round_kernel(const float* __restrict__ We)
{
    __shared__ float tile[32][33];
    int n = blockIdx.x * 32 + threadIdx.x;
    int k = blockIdx.y * 32 + threadIdx.y;
    tile[threadIdx.y][threadIdx.x] = round_tf32(We[(size_t)k * H_DIM + n]);
    __syncthreads();
    int on = blockIdx.x * 32 + threadIdx.y;
    int ok = blockIdx.y * 32 + threadIdx.x;
    g_Wt[(size_t)on * H_DIM + ok] = tile[threadIdx.x][threadIdx.y];
}

// =====================================================================
// tcgen05-only machinery
// =====================================================================
#if HAS_TCGEN05

#define MBARRIER_INIT(addr, cnt) \
    asm volatile("mbarrier.init.shared.b64 [%0], %1;" :: "r"((uint32_t)(addr)), "r"((uint32_t)(cnt)) : "memory")
#define MBARRIER_INVAL(addr) \
    asm volatile("mbarrier.inval.shared.b64 [%0];" :: "r"((uint32_t)(addr)) : "memory")
#define MBARRIER_EXPECT_TX(addr, bytes) \
    asm volatile("mbarrier.arrive.expect_tx.shared.b64 _, [%0], %1;" \
                 :: "r"((uint32_t)(addr)), "r"((uint32_t)(bytes)) : "memory")
#define MBARRIER_WAIT_PARITY(mbar, parity) do {                                   \
    asm volatile(                                                                 \
        "{\n\t.reg .pred P1;\n\t"                                                 \
        "WAIT_LOOP_%=:\n\t"                                                       \
        "mbarrier.try_wait.parity.acquire.cta.shared::cta.b64 P1, [%0], %1, 0x989680;\n\t" \
        "@P1 bra.uni WAIT_DONE_%=;\n\t"                                           \
        "bra.uni WAIT_LOOP_%=;\n\t"                                               \
        "WAIT_DONE_%=:\n\t}"                                                      \
        :: "r"((uint32_t)(mbar)), "r"((uint32_t)(parity)) : "memory");            \
} while (0)

#define CLUSTER_SYNC() do {                                              \
    asm volatile("barrier.cluster.arrive.aligned;" ::: "memory");        \
    asm volatile("barrier.cluster.wait.aligned;" ::: "memory");          \
} while (0)

#define TCGEN05_ALLOC_CG2(sres, n) \
    asm volatile("tcgen05.alloc.cta_group::2.sync.aligned.shared::cta.b32 [%0], %1;" \
                 :: "r"((uint32_t)(sres)), "r"((uint32_t)(n)) : "memory")
#define TCGEN05_DEALLOC_CG2(tm, n) \
    asm volatile("tcgen05.dealloc.cta_group::2.sync.aligned.b32 %0, %1;" :: "r"(tm), "r"((uint32_t)(n)))
#define TCGEN05_RELINQ_CG2() \
    asm volatile("tcgen05.relinquish_alloc_permit.cta_group::2.sync.aligned;")
#define TCGEN05_COMMIT_MC_CG2(mbar, mask) \
    asm volatile("tcgen05.commit.cta_group::2.mbarrier::arrive::one.shared::cluster.multicast::cluster.b64 [%0], %1;" \
                 :: "r"((uint32_t)(mbar)), "h"((uint16_t)(mask)) : "memory")
#define TCGEN05_FENCE_AFTER()  asm volatile("tcgen05.fence::after_thread_sync;" ::: "memory")
#define TCGEN05_FENCE_BEFORE() asm volatile("tcgen05.fence::before_thread_sync;" ::: "memory")
#define TCGEN05_WAIT_LD()      asm volatile("tcgen05.wait::ld.sync.aligned;" ::: "memory")

// cg2 TMA: both CTAs execute; complete_tx routes to the LEADER's barrier
// (clear bit 24 = Sm100MmaPeerBitMask), data lands in the executing CTA's SMEM.
#define TMA_LOAD_2D_CG2(smem_addr, tmap, cx, cy, mbar)                            \
    asm volatile(                                                                 \
        "{\n\t.reg .b32 lb;\n\t"                                                  \
        "and.b32 lb, %4, 0xFEFFFFFF;\n\t"                                         \
        "cp.async.bulk.tensor.2d.cta_group::2.shared::cluster.global.tile.mbarrier::complete_tx::bytes " \
        "[%0], [%1, {%2, %3}], [lb];\n\t}"                                        \
        :: "r"((uint32_t)(smem_addr)), "l"(tmap), "r"((int32_t)(cx)),             \
           "r"((int32_t)(cy)), "r"((uint32_t)(mbar)) : "memory")

#define TCGEN05_LD_32X32B_X32(r, tmem_addr)                                     \
    asm volatile(                                                               \
        "tcgen05.ld.sync.aligned.32x32b.x32.b32 "                               \
        "{%0, %1, %2, %3, %4, %5, %6, %7, "                                     \
        " %8, %9, %10, %11, %12, %13, %14, %15, "                               \
        " %16, %17, %18, %19, %20, %21, %22, %23, "                             \
        " %24, %25, %26, %27, %28, %29, %30, %31}, [%32];"                      \
        : "=r"((r)[0]),  "=r"((r)[1]),  "=r"((r)[2]),  "=r"((r)[3]),            \
          "=r"((r)[4]),  "=r"((r)[5]),  "=r"((r)[6]),  "=r"((r)[7]),            \
          "=r"((r)[8]),  "=r"((r)[9]),  "=r"((r)[10]), "=r"((r)[11]),           \
          "=r"((r)[12]), "=r"((r)[13]), "=r"((r)[14]), "=r"((r)[15]),           \
          "=r"((r)[16]), "=r"((r)[17]), "=r"((r)[18]), "=r"((r)[19]),           \
          "=r"((r)[20]), "=r"((r)[21]), "=r"((r)[22]), "=r"((r)[23]),           \
          "=r"((r)[24]), "=r"((r)[25]), "=r"((r)[26]), "=r"((r)[27]),           \
          "=r"((r)[28]), "=r"((r)[29]), "=r"((r)[30]), "=r"((r)[31])            \
        : "r"(tmem_addr))

static constexpr uint64_t SMEM_DESC_BASE_SW128 =
    (uint64_t(2)  << 61) | (uint64_t(1) << 46) | (uint64_t(64) << 32) | (uint64_t(1) << 16);
#define MAKE_SMEM_DESC(base) (SMEM_DESC_BASE_SW128 | ((uint64_t)((base) >> 4) & 0x3FFF))

// idesc kind::tf32, cg2: d=F32(1<<4), a=TF32(2<<7), b=TF32(2<<10),
// (N=256/8)<<17, (M=256/16)<<24  -> 0x10400910
#define GEMM_IDESC_CG2 0x10400910u

__device__ __forceinline__ void mma_tf32_ss_cg2(uint32_t d, uint64_t a, uint64_t b, uint32_t en) {
    asm volatile(
        "{\n\t.reg .pred p;\n\t"
        "setp.ne.u32 p, %4, 0;\n\t"
        "tcgen05.mma.cta_group::2.kind::tf32 [%0], %1, %2, %3, "
        "{%5, %5, %5, %5, %5, %5, %5, %5}, p;\n\t}"
        :: "r"(d), "l"(a), "l"(b), "r"(GEMM_IDESC_CG2), "r"(en), "r"(0u) : "memory");
}
#endif  // HAS_TCGEN05

// =====================================================================
// Kernel 7a: tcgen05 tf32 cg2 pair-GEMM. Tile per pair: M=256 x N=512.
// Per CTA/stage: A-half 16KB (128 rows) + B 2x16KB (its 128 N-rows of each
// N-256 block). 4-stage ring, leader-only MMA, cg2 multicast release.
// =====================================================================
#define GBM 256
#define GBN 512
#define GBK 32
#define A_ST 16384                      // 128 rows x 128 B
#define B_ST 16384                      // 128 rows x 128 B (one N-256 block half)
#define STAGE_BYTES (A_ST + 2 * B_ST)   // 49152 B
#define NSTAGES 4
#define GEMM_SMEM (3072 + NSTAGES * STAGE_BYTES)   // 199680 B

// ctrl layout from sb: 0 tmem ptr; full(s)=8+16s; empty(s)=16+16s; done=72
#define MB_FULL(s)  (sb + 8  + (s) * 16)
#define MB_EMPTY(s) (sb + 16 + (s) * 16)
#define MB_DONE     (sb + 72)

__global__ __launch_bounds__(256)
#if HAS_TCGEN05
__cluster_dims__(2, 1, 1)
#endif
void gemm_tc_kernel(const __grid_constant__ CUtensorMap tmA,
                    const __grid_constant__ CUtensorMap tmB,
                    const float* __restrict__ be, float* __restrict__ out)
{
#if HAS_TCGEN05
    extern __shared__ char smem[];
    uint32_t sb = smem_u32(smem);
    const int tid  = threadIdx.x;
    const int wid  = tid >> 5;
    const int lane = tid & 31;
    uint32_t rank;
    asm("mov.u32 %0, %%cluster_ctarank;" : "=r"(rank));
    const int colBase = (blockIdx.x >> 1) * GBN;
    const int rowBase = blockIdx.y * GBM;

    float* sBias = (float*)(smem + 128);    // 512 f32 -> [128, 2176)
    float* sBp   = (float*)(smem + 2176);   // 128 f32 -> [2176, 2688)
    const uint32_t buf0 = sb + 3072;        // 1024-aligned (dyn smem is 1KB-aligned)

    if (wid == 0) TCGEN05_ALLOC_CG2(sb + 0, 512);
    if (tid == 0) {
        #pragma unroll
        for (int s = 0; s < NSTAGES; ++s) {
            MBARRIER_INIT(MB_FULL(s), 1);
            MBARRIER_INIT(MB_EMPTY(s), 1);
        }
        MBARRIER_INIT(MB_DONE, 1);
    }
    sBias[tid]       = be[colBase + tid];
    sBias[tid + 256] = be[colBase + 256 + tid];
    if (tid < 128) sBp[tid] = g_bestp[rowBase + (int)rank * 128 + tid];
    __syncthreads();
    // peer mbarriers must be live before any cg2 TMA / multicast commit
    CLUSTER_SYNC();
    uint32_t tmem;
    asm volatile("ld.shared.b32 %0, [%1];" : "=r"(tmem) : "r"(sb + 0));

    const int NST = H_DIM / GBK;   // 32

    if (wid == 1 && elect_one_pred()) {
        // ---- producer (both CTAs): own A half + own halves of both B blocks ----
        int ph[NSTAGES] = {1, 1, 1, 1};
        for (int kt = 0; kt < NST; ++kt) {
            const int s = kt & (NSTAGES - 1);
            MBARRIER_WAIT_PARITY(MB_EMPTY(s), ph[s]); ph[s] ^= 1;
            const uint32_t ab = buf0 + s * STAGE_BYTES;
            if (rank == 0) MBARRIER_EXPECT_TX(MB_FULL(s), 2 * STAGE_BYTES);
            TMA_LOAD_2D_CG2(ab,              &tmA, kt * GBK,
                            rowBase + (int)rank * 128, MB_FULL(s));
            TMA_LOAD_2D_CG2(ab + A_ST,       &tmB, kt * GBK,
                            colBase + (int)rank * 128, MB_FULL(s));
            TMA_LOAD_2D_CG2(ab + A_ST + B_ST, &tmB, kt * GBK,
                            colBase + 256 + (int)rank * 128, MB_FULL(s));
        }
    }
    if (rank == 0 && wid == 0 && elect_one_pred()) {
        // ---- leader MMA: two N-256 dispatches per K-chunk ----
        int ph[NSTAGES] = {0, 0, 0, 0};
        for (int kt = 0; kt < NST; ++kt) {
            const int s = kt & (NSTAGES - 1);
            MBARRIER_WAIT_PARITY(MB_FULL(s), ph[s]); ph[s] ^= 1;
            const uint32_t ab = buf0 + s * STAGE_BYTES;
            uint64_t ad  = MAKE_SMEM_DESC(ab);
            uint64_t bd0 = MAKE_SMEM_DESC(ab + A_ST);
            uint64_t bd1 = MAKE_SMEM_DESC(ab + A_ST + B_ST);
            #pragma unroll
            for (int ks = 0; ks < 4; ++ks) {
                uint32_t en = (kt | ks) != 0;
                mma_tf32_ss_cg2(tmem,       ad + ks * 2, bd0 + ks * 2, en);
                mma_tf32_ss_cg2(tmem + 256, ad + ks * 2, bd1 + ks * 2, en);
            }
            TCGEN05_COMMIT_MC_CG2(MB_EMPTY(s), 0x3);
        }
        TCGEN05_COMMIT_MC_CG2(MB_DONE, 0x3);
    }

    // both CTAs: wait for all MMAs, read local 128x512 D slice
    MBARRIER_WAIT_PARITY(MB_DONE, 0);
    TCGEN05_FENCE_AFTER();

    {
        const int sub    = wid & 3;           // TMEM subpartition
        const int half   = wid >> 2;          // N-256 block
        const int rowLoc = sub * 32 + lane;   // 0..127
        const float p = sBp[rowLoc];
        const uint32_t dbase = tmem + half * 256;
        float* orow = out + (size_t)(rowBase + rank * 128 + rowLoc) * H_DIM
                          + colBase + half * 256;
        #pragma unroll
        for (int ch = 0; ch < 8; ++ch) {
            uint32_t r[32];
            TCGEN05_LD_32X32B_X32(r, dbase + ch * 32);
            TCGEN05_WAIT_LD();
            #pragma unroll
            for (int i = 0; i < 32; i += 4) {
                const int c = half * 256 + ch * 32 + i;
                float4 v;
                v.x = (__uint_as_float(r[i + 0]) + sBias[c + 0]) * p;
                v.y = (__uint_as_float(r[i + 1]) + sBias[c + 1]) * p;
                v.z = (__uint_as_float(r[i + 2]) + sBias[c + 2]) * p;
                v.w = (__uint_as_float(r[i + 3]) + sBias[c + 3]) * p;
                *(float4*)(orow + ch * 32 + i) = v;
            }
        }
        TCGEN05_FENCE_BEFORE();
    }
    __syncthreads();
    CLUSTER_SYNC();   // no teardown while peer ops may still target this CTA
    if (tid == 0) {
        #pragma unroll
        for (int s = 0; s < NSTAGES; ++s) {
            MBARRIER_INVAL(MB_FULL(s));
            MBARRIER_INVAL(MB_EMPTY(s));
        }
        MBARRIER_INVAL(MB_DONE);
    }
    __syncthreads();
    if (wid == 0) {
        TCGEN05_RELINQ_CG2();
        TCGEN05_DEALLOC_CG2(tmem, 512);
    }
    CLUSTER_SYNC();
#endif  // HAS_TCGEN05
}

// =====================================================================
// Kernel 7b: WMMA tf32 fallback 128x128 (compiled in ALL passes)
// =====================================================================
#define FBM 128
#define FBN 128
#define FBK 16
#define FLD 20
#define FNKT (H_DIM / FBK)
#define FB_SMEM (( (2*FBM*FLD) + (2*FBN*FLD) + 8*256 + FBM + FBN ) * 4)

__global__ __launch_bounds__(256) void gemm_wmma_kernel(
    const float* __restrict__ be, float* __restrict__ out)
{
    extern __shared__ float fsm[];
    float* As    = fsm;
    float* Bs    = As + 2 * FBM * FLD;
    float* sC    = Bs + 2 * FBN * FLD;
    float* sBias = sC + 8 * 256;
    float* sBp   = sBias + FBN;

    const int tid = threadIdx.x;
    const int rowBase = blockIdx.y * FBM;
    const int colBase = blockIdx.x * FBN;

    if (tid < FBM)       sBp[tid]         = g_bestp[rowBase + tid];
    else                 sBias[tid - FBM] = be[colBase + tid - FBM];

    const int arow = tid >> 1;
    const int aseg = (tid & 1) * 8;
    const float* aSrc = g_A  + (size_t)(rowBase + arow) * H_DIM + aseg;
    const float* bSrc = g_Wt + (size_t)(colBase + arow) * H_DIM + aseg;
    const uint32_t asm_base = smem_u32(As);
    const uint32_t bsm_base = smem_u32(Bs);

    auto load_tiles = [&](int buf, int kt) {
        const int k0 = kt * FBK;
        uint32_t ao = asm_base + (buf * FBM * FLD + arow * FLD + aseg) * 4;
        uint32_t bo = bsm_base + (buf * FBN * FLD + arow * FLD + aseg) * 4;
        cp16(ao,      aSrc + k0);
        cp16(ao + 16, aSrc + k0 + 4);
        cp16(bo,      bSrc + k0);
        cp16(bo + 16, bSrc + k0 + 4);
    };

    const int warpId = tid >> 5;
    const int wm = warpId >> 2;
    const int wn = warpId & 3;

    wmma::fragment<wmma::accumulator, 16, 16, 8, float> acc[4][2];
    #pragma unroll
    for (int mi = 0; mi < 4; ++mi)
        #pragma unroll
        for (int ni = 0; ni < 2; ++ni)
            wmma::fill_fragment(acc[mi][ni], 0.0f);

    load_tiles(0, 0);
    cp_commit();

    for (int kt = 0; kt < FNKT; ++kt) {
        if (kt + 1 < FNKT) {
            load_tiles((kt + 1) & 1, kt + 1);
            cp_commit();
            cp_wait<1>();
        } else {
            cp_wait<0>();
        }
        __syncthreads();

        const int buf = kt & 1;
        #pragma unroll
        for (int ks = 0; ks < 2; ++ks) {
            wmma::fragment<wmma::matrix_a, 16, 16, 8, wmma::precision::tf32,
                           wmma::row_major> af[4];
            wmma::fragment<wmma::matrix_b, 16, 16, 8, wmma::precision::tf32,
                           wmma::col_major> bf[2];
            #pragma unroll
            for (int mi = 0; mi < 4; ++mi)
                wmma::load_matrix_sync(
                    af[mi], &As[buf * FBM * FLD + (wm * 64 + mi * 16) * FLD + ks * 8], FLD);
            #pragma unroll
            for (int ni = 0; ni < 2; ++ni)
                wmma::load_matrix_sync(
                    bf[ni], &Bs[buf * FBN * FLD + (wn * 32 + ni * 16) * FLD + ks * 8], FLD);
            #pragma unroll
            for (int mi = 0; mi < 4; ++mi)
                #pragma unroll
                for (int ni = 0; ni < 2; ++ni)
                    wmma::mma_sync(acc[mi][ni], af[mi], bf[ni], acc[mi][ni]);
        }
        __syncthreads();
    }

    const int lane = tid & 31;
    float* stg = &sC[warpId * 256];
    #pragma unroll
    for (int mi = 0; mi < 4; ++mi) {
        #pragma unroll
        for (int ni = 0; ni < 2; ++ni) {
            wmma::store_matrix_sync(stg, acc[mi][ni], 16, wmma::mem_row_major);
            __syncwarp();
            const int r = lane >> 1;
            const int c = (lane & 1) * 8;
            const int rowL = wm * 64 + mi * 16 + r;
            const int colL = wn * 32 + ni * 16 + c;
            const float p = sBp[rowL];
            float4 v0 = *(const float4*)&stg[r * 16 + c];
            float4 v1 = *(const float4*)&stg[r * 16 + c + 4];
            float4 o0, o1;
            o0.x = (v0.x + sBias[colL + 0]) * p;
            o0.y = (v0.y + sBias[colL + 1]) * p;
            o0.z = (v0.z + sBias[colL + 2]) * p;
            o0.w = (v0.w + sBias[colL + 3]) * p;
            o1.x = (v1.x + sBias[colL + 4]) * p;
            o1.y = (v1.y + sBias[colL + 5]) * p;
            o1.z = (v1.z + sBias[colL + 6]) * p;
            o1.w = (v1.w + sBias[colL + 7]) * p;
            float* dst = out + (size_t)(rowBase + rowL) * H_DIM + colBase + colL;
            *(float4*)(dst + 0) = o0;
            *(float4*)(dst + 4) = o1;
            __syncwarp();
        }
    }
}

// =====================================================================
// host: tensor-map construction via driver entry point (no -lcuda link)
// =====================================================================
typedef CUresult (*PFN_encodeTiled)(
    CUtensorMap*, CUtensorMapDataType, cuuint32_t, void*,
    const cuuint64_t*, const cuuint64_t*, const cuuint32_t*, const cuuint32_t*,
    CUtensorMapInterleave, CUtensorMapSwizzle, CUtensorMapL2promotion,
    CUtensorMapFloatOOBfill);

static PFN_encodeTiled get_encode_fn()
{
    void* fn = nullptr;
    cudaDriverEntryPointQueryResult qres = cudaDriverEntryPointSymbolNotFound;
#if CUDART_VERSION >= 12050
    cudaGetDriverEntryPointByVersion("cuTensorMapEncodeTiled", &fn, 12000,
                                     cudaEnableDefault, &qres);
#else
    cudaGetDriverEntryPoint("cuTensorMapEncodeTiled", &fn,
                            cudaEnableDefault, &qres);
#endif
    if (qres != cudaDriverEntryPointSuccess) return nullptr;
    return (PFN_encodeTiled)fn;
}

static bool make_map(PFN_encodeTiled enc, CUtensorMap* tm, void* base,
                     uint64_t d0, uint64_t d1, uint32_t b0, uint32_t b1)
{
    cuuint64_t dims[2]    = {d0, d1};
    cuuint64_t strides[1] = {d0 * 4};
    cuuint32_t box[2]     = {b0, b1};
    cuuint32_t es[2]      = {1, 1};
    CUresult r = enc(tm, CU_TENSOR_MAP_DATA_TYPE_FLOAT32, 2, base,
                     dims, strides, box, es,
                     CU_TENSOR_MAP_INTERLEAVE_NONE, CU_TENSOR_MAP_SWIZZLE_128B,
                     CU_TENSOR_MAP_L2_PROMOTION_L2_128B,
                     CU_TENSOR_MAP_FLOAT_OOB_FILL_NONE);
    return r == CUDA_SUCCESS;
}

// =====================================================================
// launch
// =====================================================================
extern "C" void kernel_launch(void* const* d_in, const int* in_sizes, int n_in,
                              void* d_out, int out_size)
{
    const float* x  = (const float*)d_in[0];
    const float* Wr = (const float*)d_in[1];
    const float* br = (const float*)d_in[2];
    const float* We = (const float*)d_in[3];
    const float* be = (const float*)d_in[4];
    float* out = (float*)d_out;

    const int T  = in_sizes[0] / H_DIM;   // 32768
    const int NB = T / 256;

    router_kernel<<<T / 32, 256>>>(x, Wr, br, T);
    transpose_round_kernel<<<dim3(H_DIM / 32, H_DIM / 32), dim3(32, 32)>>>(We);
    hist_kernel<<<NB, 256>>>(T);
    offsets_kernel<<<1, 256>>>(NB);
    scatter_kernel<<<NB, 256>>>(T);
    gather_round_kernel<<<T, 256>>>(x);

    // which GEMM variant is live in this binary?
    cudaFuncAttributes attr;
    attr.numRegs = 0;
    cudaFuncGetAttributes(&attr, (const void*)gemm_tc_kernel);

    bool tc_ok = (attr.numRegs > 32);
    CUtensorMap tmA, tmB;
    if (tc_ok) {
        PFN_encodeTiled enc = get_encode_fn();
        void *pA = nullptr, *pW = nullptr;
        tc_ok = enc != nullptr
             && cudaGetSymbolAddress(&pA, g_A)  == cudaSuccess
             && cudaGetSymbolAddress(&pW, g_Wt) == cudaSuccess
             && make_map(enc, &tmA, pA, H_DIM, (uint64_t)T, GBK, 128)   // A half box 32x128
             && make_map(enc, &tmB, pW, H_DIM, H_DIM,       GBK, 128);  // B half box 32x128
    }

    if (tc_ok) {
        cudaFuncSetAttribute(gemm_tc_kernel,
                             cudaFuncAttributeMaxDynamicSharedMemorySize, GEMM_SMEM);
        dim3 gtc(2 * (H_DIM / GBN), T / GBM);   // (4, 128); x pairs = clusters of 2
        gemm_tc_kernel<<<gtc, 256, GEMM_SMEM>>>(tmA, tmB, be, out);
    } else {
        cudaFuncSetAttribute(gemm_wmma_kernel,
                             cudaFuncAttributeMaxDynamicSharedMemorySize, FB_SMEM);
        dim3 gfb(H_DIM / FBN, T / FBM);   // (8, 256)
        gemm_wmma_kernel<<<gfb, 256, FB_SMEM>>>(be, out);
    }
}

// round 9
// speedup vs baseline: 1.1682x; 1.0882x over previous
#include <cuda_runtime.h>
#include <cuda.h>
#include <mma.h>
#include <cstdint>

using namespace nvcuda;

#define T_MAX 32768
#define H_DIM 1024
#define E_DIM 8

// tcgen05 is only legal in arch-accelerated (sm_10xa) compilation passes.
#if defined(__CUDA_ARCH_FEAT_SM103_ALL) || defined(__CUDA_ARCH_FEAT_SM100_ALL) || defined(__CUDA_ARCH_FEAT_SM101_ALL)
#define HAS_TCGEN05 1
#else
#define HAS_TCGEN05 0
#endif

// ---------------- scratch (no runtime allocations allowed) ----------------
__device__ int   g_best [T_MAX];
__device__ float g_bestp[T_MAX];
__device__ int   g_order[T_MAX];
__device__ int   g_inv  [T_MAX];        // inv_order: source row s -> output row t
#define NB_MAX (T_MAX / 256)
__device__ int g_hist[NB_MAX * E_DIM];
__device__ int g_boff[NB_MAX * E_DIM];
__device__ float g_A [T_MAX * H_DIM];   // NATURAL-order x, RN-rounded to tf32
__device__ float g_Wt[H_DIM * H_DIM];   // W_expert transposed ([N,K]) + RN tf32

// ---------------- generic helpers ----------------
__device__ __forceinline__ uint32_t smem_u32(const void* p) {
    uint32_t a;
    asm("{ .reg .u64 t; cvta.to.shared.u64 t, %1; cvt.u32.u64 %0, t; }" : "=r"(a) : "l"(p));
    return a;
}
__device__ __forceinline__ float round_tf32(float v) {
    uint32_t o;
    asm("cvt.rna.tf32.f32 %0, %1;" : "=r"(o) : "f"(v));
    return __uint_as_float(o);
}
__device__ __forceinline__ void cp16(uint32_t saddr, const void* g) {
    asm volatile("cp.async.cg.shared.global [%0], [%1], 16;\n" :: "r"(saddr), "l"(g));
}
__device__ __forceinline__ void cp_commit() { asm volatile("cp.async.commit_group;\n"); }
template <int N> __device__ __forceinline__ void cp_wait() {
    asm volatile("cp.async.wait_group %0;\n" :: "n"(N));
}

__device__ __forceinline__ uint32_t elect_one_pred() {
    uint32_t pred;
    asm volatile(
        "{\n\t.reg .pred p;\n\t"
        "elect.sync _|p, 0xFFFFFFFF;\n\t"
        "selp.b32 %0, 1, 0, p;\n\t}"
        : "=r"(pred));
    return pred;
}

// =====================================================================
// Kernel 1: router — logits math UNCHANGED (defines the permutation);
// additionally stores RN-tf32-rounded x into g_A (kills the gather pass)
// =====================================================================
__global__ __launch_bounds__(256) void router_kernel(
    const float* __restrict__ x, const float* __restrict__ Wr,
    const float* __restrict__ br, int T)
{
    __shared__ float sW[E_DIM][H_DIM];
    for (int i = threadIdx.x; i < H_DIM * E_DIM; i += 256) {
        int h = i >> 3, e = i & 7;
        sW[e][h] = Wr[i];
    }
    __syncthreads();

    int warp = threadIdx.x >> 5;
    int lane = threadIdx.x & 31;
    int tokBase = blockIdx.x * 32 + warp * 4;

    for (int tt = 0; tt < 4; ++tt) {
        int t = tokBase + tt;
        if (t >= T) break;
        const float* xr = x + (size_t)t * H_DIM;
        float*       ar = g_A + (size_t)t * H_DIM;

        float acc[E_DIM];
        #pragma unroll
        for (int e = 0; e < E_DIM; ++e) acc[e] = 0.f;
        #pragma unroll 4
        for (int i = 0; i < H_DIM / 32; ++i) {
            float xv = xr[i * 32 + lane];
            ar[i * 32 + lane] = round_tf32(xv);        // fused rounded store
            #pragma unroll
            for (int e = 0; e < E_DIM; ++e) acc[e] += xv * sW[e][i * 32 + lane];
        }
        #pragma unroll
        for (int e = 0; e < E_DIM; ++e) {
            #pragma unroll
            for (int off = 16; off; off >>= 1)
                acc[e] += __shfl_down_sync(0xffffffffu, acc[e], off);
        }
        if (lane == 0) {
            float l[E_DIM];
            #pragma unroll
            for (int e = 0; e < E_DIM; ++e) l[e] = acc[e] + br[e];
            int bi = 0; float bm = l[0];
            #pragma unroll
            for (int e = 1; e < E_DIM; ++e)
                if (l[e] > bm) { bm = l[e]; bi = e; }
            float s = 0.f;
            #pragma unroll
            for (int e = 0; e < E_DIM; ++e) s += expf(l[e] - bm);
            g_best [t] = bi;
            g_bestp[t] = 1.0f / s;
        }
    }
}

// =====================================================================
// Kernels 2-4: stable counting sort
// =====================================================================
__global__ void hist_kernel(int T)
{
    __shared__ int sh[E_DIM];
    if (threadIdx.x < E_DIM) sh[threadIdx.x] = 0;
    __syncthreads();
    int t = blockIdx.x * 256 + threadIdx.x;
    if (t < T) atomicAdd(&sh[g_best[t]], 1);
    __syncthreads();
    if (threadIdx.x < E_DIM)
        g_hist[blockIdx.x * E_DIM + threadIdx.x] = sh[threadIdx.x];
}

__global__ __launch_bounds__(256) void offsets_kernel(int NB)
{
    __shared__ int sh[NB_MAX * E_DIM];
    __shared__ int tot[E_DIM];
    __shared__ int base[E_DIM];
    const int tid = threadIdx.x;
    for (int i = tid; i < NB * E_DIM; i += 256) sh[i] = g_hist[i];
    __syncthreads();

    const int w = tid >> 5, l = tid & 31;
    if (w < E_DIM) {
        int run = 0;
        for (int c = 0; c < NB; c += 32) {
            int v = sh[(c + l) * E_DIM + w];
            int xs = v;
            #pragma unroll
            for (int off = 1; off < 32; off <<= 1) {
                int y = __shfl_up_sync(0xffffffffu, xs, off);
                if (l >= off) xs += y;
            }
            sh[(c + l) * E_DIM + w] = xs - v + run;
            run += __shfl_sync(0xffffffffu, xs, 31);
        }
        if (l == 0) tot[w] = run;
    }
    __syncthreads();
    if (tid == 0) {
        int b = 0;
        #pragma unroll
        for (int e = 0; e < E_DIM; ++e) { base[e] = b; b += tot[e]; }
    }
    __syncthreads();
    for (int i = tid; i < NB * E_DIM; i += 256)
        g_boff[i] = sh[i] + base[i & (E_DIM - 1)];
}

__global__ void scatter_kernel(int T)
{
    __shared__ int sb[256];
    int i = threadIdx.x;
    int t = blockIdx.x * 256 + i;
    sb[i] = (t < T) ? g_best[t] : -1;
    __syncthreads();
    if (t < T) {
        int e = sb[i];
        int rank = 0;
        for (int j = 0; j < i; ++j) rank += (sb[j] == e);
        int pos = g_boff[blockIdx.x * E_DIM + e] + rank;
        g_order[pos] = t;
        g_inv[t]     = pos;        // source row t lands in output row pos
    }
}

// =====================================================================
// Kernel 5: transpose W_expert -> [N,K] with RN tf32 rounding
// =====================================================================
__global__ void transpose_round_kernel(const float* __restrict__ We)
{
    __shared__ float tile[32][33];
    int n = blockIdx.x * 32 + threadIdx.x;
    int k = blockIdx.y * 32 + threadIdx.y;
    tile[threadIdx.y][threadIdx.x] = round_tf32(We[(size_t)k * H_DIM + n]);
    __syncthreads();
    int on = blockIdx.x * 32 + threadIdx.y;
    int ok = blockIdx.y * 32 + threadIdx.x;
    g_Wt[(size_t)on * H_DIM + ok] = tile[threadIdx.x][threadIdx.y];
}

// =====================================================================
// tcgen05-only machinery
// =====================================================================
#if HAS_TCGEN05

#define MBARRIER_INIT(addr, cnt) \
    asm volatile("mbarrier.init.shared.b64 [%0], %1;" :: "r"((uint32_t)(addr)), "r"((uint32_t)(cnt)) : "memory")
#define MBARRIER_INVAL(addr) \
    asm volatile("mbarrier.inval.shared.b64 [%0];" :: "r"((uint32_t)(addr)) : "memory")
#define MBARRIER_EXPECT_TX(addr, bytes) \
    asm volatile("mbarrier.arrive.expect_tx.shared.b64 _, [%0], %1;" \
                 :: "r"((uint32_t)(addr)), "r"((uint32_t)(bytes)) : "memory")
#define MBARRIER_WAIT_PARITY(mbar, parity) do {                                   \
    asm volatile(                                                                 \
        "{\n\t.reg .pred P1;\n\t"                                                 \
        "WAIT_LOOP_%=:\n\t"                                                       \
        "mbarrier.try_wait.parity.acquire.cta.shared::cta.b64 P1, [%0], %1, 0x989680;\n\t" \
        "@P1 bra.uni WAIT_DONE_%=;\n\t"                                           \
        "bra.uni WAIT_LOOP_%=;\n\t"                                               \
        "WAIT_DONE_%=:\n\t}"                                                      \
        :: "r"((uint32_t)(mbar)), "r"((uint32_t)(parity)) : "memory");            \
} while (0)

#define CLUSTER_SYNC() do {                                              \
    asm volatile("barrier.cluster.arrive.aligned;" ::: "memory");        \
    asm volatile("barrier.cluster.wait.aligned;" ::: "memory");          \
} while (0)

#define TCGEN05_ALLOC_CG2(sres, n) \
    asm volatile("tcgen05.alloc.cta_group::2.sync.aligned.shared::cta.b32 [%0], %1;" \
                 :: "r"((uint32_t)(sres)), "r"((uint32_t)(n)) : "memory")
#define TCGEN05_DEALLOC_CG2(tm, n) \
    asm volatile("tcgen05.dealloc.cta_group::2.sync.aligned.b32 %0, %1;" :: "r"(tm), "r"((uint32_t)(n)))
#define TCGEN05_RELINQ_CG2() \
    asm volatile("tcgen05.relinquish_alloc_permit.cta_group::2.sync.aligned;")
#define TCGEN05_COMMIT_MC_CG2(mbar, mask) \
    asm volatile("tcgen05.commit.cta_group::2.mbarrier::arrive::one.shared::cluster.multicast::cluster.b64 [%0], %1;" \
                 :: "r"((uint32_t)(mbar)), "h"((uint16_t)(mask)) : "memory")
#define TCGEN05_FENCE_AFTER()  asm volatile("tcgen05.fence::after_thread_sync;" ::: "memory")
#define TCGEN05_FENCE_BEFORE() asm volatile("tcgen05.fence::before_thread_sync;" ::: "memory")
#define TCGEN05_WAIT_LD()      asm volatile("tcgen05.wait::ld.sync.aligned;" ::: "memory")

// cg2 TMA: both CTAs execute; complete_tx routes to the LEADER's barrier
// (clear bit 24 = Sm100MmaPeerBitMask), data lands in the executing CTA's SMEM.
#define TMA_LOAD_2D_CG2(smem_addr, tmap, cx, cy, mbar)                            \
    asm volatile(                                                                 \
        "{\n\t.reg .b32 lb;\n\t"                                                  \
        "and.b32 lb, %4, 0xFEFFFFFF;\n\t"                                         \
        "cp.async.bulk.tensor.2d.cta_group::2.shared::cluster.global.tile.mbarrier::complete_tx::bytes " \
        "[%0], [%1, {%2, %3}], [lb];\n\t}"                                        \
        :: "r"((uint32_t)(smem_addr)), "l"(tmap), "r"((int32_t)(cx)),             \
           "r"((int32_t)(cy)), "r"((uint32_t)(mbar)) : "memory")

#define TCGEN05_LD_32X32B_X32(r, tmem_addr)                                     \
    asm volatile(                                                               \
        "tcgen05.ld.sync.aligned.32x32b.x32.b32 "                               \
        "{%0, %1, %2, %3, %4, %5, %6, %7, "                                     \
        " %8, %9, %10, %11, %12, %13, %14, %15, "                               \
        " %16, %17, %18, %19, %20, %21, %22, %23, "                             \
        " %24, %25, %26, %27, %28, %29, %30, %31}, [%32];"                      \
        : "=r"((r)[0]),  "=r"((r)[1]),  "=r"((r)[2]),  "=r"((r)[3]),            \
          "=r"((r)[4]),  "=r"((r)[5]),  "=r"((r)[6]),  "=r"((r)[7]),            \
          "=r"((r)[8]),  "=r"((r)[9]),  "=r"((r)[10]), "=r"((r)[11]),           \
          "=r"((r)[12]), "=r"((r)[13]), "=r"((r)[14]), "=r"((r)[15]),           \
          "=r"((r)[16]), "=r"((r)[17]), "=r"((r)[18]), "=r"((r)[19]),           \
          "=r"((r)[20]), "=r"((r)[21]), "=r"((r)[22]), "=r"((r)[23]),           \
          "=r"((r)[24]), "=r"((r)[25]), "=r"((r)[26]), "=r"((r)[27]),           \
          "=r"((r)[28]), "=r"((r)[29]), "=r"((r)[30]), "=r"((r)[31])            \
        : "r"(tmem_addr))

static constexpr uint64_t SMEM_DESC_BASE_SW128 =
    (uint64_t(2)  << 61) | (uint64_t(1) << 46) | (uint64_t(64) << 32) | (uint64_t(1) << 16);
#define MAKE_SMEM_DESC(base) (SMEM_DESC_BASE_SW128 | ((uint64_t)((base) >> 4) & 0x3FFF))

// idesc kind::tf32, cg2: d=F32(1<<4), a=TF32(2<<7), b=TF32(2<<10),
// (N=256/8)<<17, (M=256/16)<<24  -> 0x10400910
#define GEMM_IDESC_CG2 0x10400910u

__device__ __forceinline__ void mma_tf32_ss_cg2(uint32_t d, uint64_t a, uint64_t b, uint32_t en) {
    asm volatile(
        "{\n\t.reg .pred p;\n\t"
        "setp.ne.u32 p, %4, 0;\n\t"
        "tcgen05.mma.cta_group::2.kind::tf32 [%0], %1, %2, %3, "
        "{%5, %5, %5, %5, %5, %5, %5, %5}, p;\n\t}"
        :: "r"(d), "l"(a), "l"(b), "r"(GEMM_IDESC_CG2), "r"(en), "r"(0u) : "memory");
}
#endif  // HAS_TCGEN05

// =====================================================================
// Kernel 6a: tcgen05 tf32 cg2 pair-GEMM, M=256 x N=512 per pair,
// A in NATURAL order; epilogue row-scatters via g_inv.
// =====================================================================
#define GBM 256
#define GBN 512
#define GBK 32
#define A_ST 16384                      // 128 rows x 128 B
#define B_ST 16384                      // 128 rows x 128 B
#define STAGE_BYTES (A_ST + 2 * B_ST)   // 49152 B
#define NSTAGES 4
#define GEMM_SMEM (4096 + NSTAGES * STAGE_BYTES)   // 200704 B

// ctrl layout from sb: 0 tmem ptr; full(s)=8+16s; empty(s)=16+16s; done=72
#define MB_FULL(s)  (sb + 8  + (s) * 16)
#define MB_EMPTY(s) (sb + 16 + (s) * 16)
#define MB_DONE     (sb + 72)

__global__ __launch_bounds__(256)
#if HAS_TCGEN05
__cluster_dims__(2, 1, 1)
#endif
void gemm_tc_kernel(const __grid_constant__ CUtensorMap tmA,
                    const __grid_constant__ CUtensorMap tmB,
                    const float* __restrict__ be, float* __restrict__ out)
{
#if HAS_TCGEN05
    extern __shared__ char smem[];
    uint32_t sb = smem_u32(smem);
    const int tid  = threadIdx.x;
    const int wid  = tid >> 5;
    const int lane = tid & 31;
    uint32_t rank;
    asm("mov.u32 %0, %%cluster_ctarank;" : "=r"(rank));
    const int colBase = (blockIdx.x >> 1) * GBN;
    const int rowBase = blockIdx.y * GBM;

    float* sBias = (float*)(smem + 128);    // 512 f32 -> [128, 2176)
    float* sBp   = (float*)(smem + 2176);   // 128 f32 -> [2176, 2688)
    int*   sTo   = (int*)  (smem + 2688);   // 128 i32 -> [2688, 3200)
    const uint32_t buf0 = sb + 4096;

    if (wid == 0) TCGEN05_ALLOC_CG2(sb + 0, 512);
    if (tid == 0) {
        #pragma unroll
        for (int s = 0; s < NSTAGES; ++s) {
            MBARRIER_INIT(MB_FULL(s), 1);
            MBARRIER_INIT(MB_EMPTY(s), 1);
        }
        MBARRIER_INIT(MB_DONE, 1);
    }
    sBias[tid]       = be[colBase + tid];
    sBias[tid + 256] = be[colBase + 256 + tid];
    if (tid < 128) {
        int srow = rowBase + (int)rank * 128 + tid;   // source row (natural)
        int trow = g_inv[srow];                       // output row
        sTo[tid] = trow;
        sBp[tid] = g_bestp[trow];
    }
    __syncthreads();
    CLUSTER_SYNC();   // peer mbarriers live before any cg2 TMA / multicast commit
    uint32_t tmem;
    asm volatile("ld.shared.b32 %0, [%1];" : "=r"(tmem) : "r"(sb + 0));

    const int NST = H_DIM / GBK;   // 32

    if (wid == 1 && elect_one_pred()) {
        // ---- producer (both CTAs): own A half + own halves of both B blocks ----
        int ph[NSTAGES] = {1, 1, 1, 1};
        for (int kt = 0; kt < NST; ++kt) {
            const int s = kt & (NSTAGES - 1);
            MBARRIER_WAIT_PARITY(MB_EMPTY(s), ph[s]); ph[s] ^= 1;
            const uint32_t ab = buf0 + s * STAGE_BYTES;
            if (rank == 0) MBARRIER_EXPECT_TX(MB_FULL(s), 2 * STAGE_BYTES);
            TMA_LOAD_2D_CG2(ab,               &tmA, kt * GBK,
                            rowBase + (int)rank * 128, MB_FULL(s));
            TMA_LOAD_2D_CG2(ab + A_ST,        &tmB, kt * GBK,
                            colBase + (int)rank * 128, MB_FULL(s));
            TMA_LOAD_2D_CG2(ab + A_ST + B_ST, &tmB, kt * GBK,
                            colBase + 256 + (int)rank * 128, MB_FULL(s));
        }
    }
    if (rank == 0 && wid == 0 && elect_one_pred()) {
        // ---- leader MMA: two N-256 dispatches per K-chunk ----
        int ph[NSTAGES] = {0, 0, 0, 0};
        for (int kt = 0; kt < NST; ++kt) {
            const int s = kt & (NSTAGES - 1);
            MBARRIER_WAIT_PARITY(MB_FULL(s), ph[s]); ph[s] ^= 1;
            const uint32_t ab = buf0 + s * STAGE_BYTES;
            uint64_t ad  = MAKE_SMEM_DESC(ab);
            uint64_t bd0 = MAKE_SMEM_DESC(ab + A_ST);
            uint64_t bd1 = MAKE_SMEM_DESC(ab + A_ST + B_ST);
            #pragma unroll
            for (int ks = 0; ks < 4; ++ks) {
                uint32_t en = (kt | ks) != 0;
                mma_tf32_ss_cg2(tmem,       ad + ks * 2, bd0 + ks * 2, en);
                mma_tf32_ss_cg2(tmem + 256, ad + ks * 2, bd1 + ks * 2, en);
            }
            TCGEN05_COMMIT_MC_CG2(MB_EMPTY(s), 0x3);
        }
        TCGEN05_COMMIT_MC_CG2(MB_DONE, 0x3);
    }

    // both CTAs: wait for all MMAs, read local 128x512 D slice, scatter rows
    MBARRIER_WAIT_PARITY(MB_DONE, 0);
    TCGEN05_FENCE_AFTER();

    {
        const int sub    = wid & 3;           // TMEM subpartition
        const int half   = wid >> 2;          // N-256 block
        const int rowLoc = sub * 32 + lane;   // 0..127
        const float p = sBp[rowLoc];
        const uint32_t dbase = tmem + half * 256;
        float* orow = out + (size_t)sTo[rowLoc] * H_DIM + colBase + half * 256;
        #pragma unroll
        for (int ch = 0; ch < 8; ++ch) {
            uint32_t r[32];
            TCGEN05_LD_32X32B_X32(r, dbase + ch * 32);
            TCGEN05_WAIT_LD();
            #pragma unroll
            for (int i = 0; i < 32; i += 4) {
                const int c = half * 256 + ch * 32 + i;
                float4 v;
                v.x = (__uint_as_float(r[i + 0]) + sBias[c + 0]) * p;
                v.y = (__uint_as_float(r[i + 1]) + sBias[c + 1]) * p;
                v.z = (__uint_as_float(r[i + 2]) + sBias[c + 2]) * p;
                v.w = (__uint_as_float(r[i + 3]) + sBias[c + 3]) * p;
                *(float4*)(orow + ch * 32 + i) = v;
            }
        }
        TCGEN05_FENCE_BEFORE();
    }
    __syncthreads();
    CLUSTER_SYNC();   // no teardown while peer ops may still target this CTA
    if (tid == 0) {
        #pragma unroll
        for (int s = 0; s < NSTAGES; ++s) {
            MBARRIER_INVAL(MB_FULL(s));
            MBARRIER_INVAL(MB_EMPTY(s));
        }
        MBARRIER_INVAL(MB_DONE);
    }
    __syncthreads();
    if (wid == 0) {
        TCGEN05_RELINQ_CG2();
        TCGEN05_DEALLOC_CG2(tmem, 512);
    }
    CLUSTER_SYNC();
#endif  // HAS_TCGEN05
}

// =====================================================================
// Kernel 6b: WMMA tf32 fallback 128x128 (ALL passes) — natural-order A,
// row-scatter epilogue via g_inv.
// =====================================================================
#define FBM 128
#define FBN 128
#define FBK 16
#define FLD 20
#define FNKT (H_DIM / FBK)
#define FB_SMEM (( (2*FBM*FLD) + (2*FBN*FLD) + 8*256 + FBM + FBN + FBM ) * 4)

__global__ __launch_bounds__(256) void gemm_wmma_kernel(
    const float* __restrict__ be, float* __restrict__ out)
{
    extern __shared__ float fsm[];
    float* As    = fsm;
    float* Bs    = As + 2 * FBM * FLD;
    float* sC    = Bs + 2 * FBN * FLD;
    float* sBias = sC + 8 * 256;
    float* sBp   = sBias + FBN;
    int*   sTo   = (int*)(sBp + FBM);

    const int tid = threadIdx.x;
    const int rowBase = blockIdx.y * FBM;
    const int colBase = blockIdx.x * FBN;

    if (tid < FBM) {
        int trow = g_inv[rowBase + tid];
        sTo[tid] = trow;
        sBp[tid] = g_bestp[trow];
    } else {
        sBias[tid - FBM] = be[colBase + tid - FBM];
    }

    const int arow = tid >> 1;
    const int aseg = (tid & 1) * 8;
    const float* aSrc = g_A  + (size_t)(rowBase + arow) * H_DIM + aseg;
    const float* bSrc = g_Wt + (size_t)(colBase + arow) * H_DIM + aseg;
    const uint32_t asm_base = smem_u32(As);
    const uint32_t bsm_base = smem_u32(Bs);

    auto load_tiles = [&](int buf, int kt) {
        const int k0 = kt * FBK;
        uint32_t ao = asm_base + (buf * FBM * FLD + arow * FLD + aseg) * 4;
        uint32_t bo = bsm_base + (buf * FBN * FLD + arow * FLD + aseg) * 4;
        cp16(ao,      aSrc + k0);
        cp16(ao + 16, aSrc + k0 + 4);
        cp16(bo,      bSrc + k0);
        cp16(bo + 16, bSrc + k0 + 4);
    };

    const int warpId = tid >> 5;
    const int wm = warpId >> 2;
    const int wn = warpId & 3;

    wmma::fragment<wmma::accumulator, 16, 16, 8, float> acc[4][2];
    #pragma unroll
    for (int mi = 0; mi < 4; ++mi)
        #pragma unroll
        for (int ni = 0; ni < 2; ++ni)
            wmma::fill_fragment(acc[mi][ni], 0.0f);

    load_tiles(0, 0);
    cp_commit();

    for (int kt = 0; kt < FNKT; ++kt) {
        if (kt + 1 < FNKT) {
            load_tiles((kt + 1) & 1, kt + 1);
            cp_commit();
            cp_wait<1>();
        } else {
            cp_wait<0>();
        }
        __syncthreads();

        const int buf = kt & 1;
        #pragma unroll
        for (int ks = 0; ks < 2; ++ks) {
            wmma::fragment<wmma::matrix_a, 16, 16, 8, wmma::precision::tf32,
                           wmma::row_major> af[4];
            wmma::fragment<wmma::matrix_b, 16, 16, 8, wmma::precision::tf32,
                           wmma::col_major> bf[2];
            #pragma unroll
            for (int mi = 0; mi < 4; ++mi)
                wmma::load_matrix_sync(
                    af[mi], &As[buf * FBM * FLD + (wm * 64 + mi * 16) * FLD + ks * 8], FLD);
            #pragma unroll
            for (int ni = 0; ni < 2; ++ni)
                wmma::load_matrix_sync(
                    bf[ni], &Bs[buf * FBN * FLD + (wn * 32 + ni * 16) * FLD + ks * 8], FLD);
            #pragma unroll
            for (int mi = 0; mi < 4; ++mi)
                #pragma unroll
                for (int ni = 0; ni < 2; ++ni)
                    wmma::mma_sync(acc[mi][ni], af[mi], bf[ni], acc[mi][ni]);
        }
        __syncthreads();
    }

    const int lane = tid & 31;
    float* stg = &sC[warpId * 256];
    #pragma unroll
    for (int mi = 0; mi < 4; ++mi) {
        #pragma unroll
        for (int ni = 0; ni < 2; ++ni) {
            wmma::store_matrix_sync(stg, acc[mi][ni], 16, wmma::mem_row_major);
            __syncwarp();
            const int r = lane >> 1;
            const int c = (lane & 1) * 8;
            const int rowL = wm * 64 + mi * 16 + r;
            const int colL = wn * 32 + ni * 16 + c;
            const float p = sBp[rowL];
            float4 v0 = *(const float4*)&stg[r * 16 + c];
            float4 v1 = *(const float4*)&stg[r * 16 + c + 4];
            float4 o0, o1;
            o0.x = (v0.x + sBias[colL + 0]) * p;
            o0.y = (v0.y + sBias[colL + 1]) * p;
            o0.z = (v0.z + sBias[colL + 2]) * p;
            o0.w = (v0.w + sBias[colL + 3]) * p;
            o1.x = (v1.x + sBias[colL + 4]) * p;
            o1.y = (v1.y + sBias[colL + 5]) * p;
            o1.z = (v1.z + sBias[colL + 6]) * p;
            o1.w = (v1.w + sBias[colL + 7]) * p;
            float* dst = out + (size_t)sTo[rowL] * H_DIM + colBase + colL;
            *(float4*)(dst + 0) = o0;
            *(float4*)(dst + 4) = o1;
            __syncwarp();
        }
    }
}

// =====================================================================
// host: tensor-map construction via driver entry point (no -lcuda link)
// =====================================================================
typedef CUresult (*PFN_encodeTiled)(
    CUtensorMap*, CUtensorMapDataType, cuuint32_t, void*,
    const cuuint64_t*, const cuuint64_t*, const cuuint32_t*, const cuuint32_t*,
    CUtensorMapInterleave, CUtensorMapSwizzle, CUtensorMapL2promotion,
    CUtensorMapFloatOOBfill);

static PFN_encodeTiled get_encode_fn()
{
    void* fn = nullptr;
    cudaDriverEntryPointQueryResult qres = cudaDriverEntryPointSymbolNotFound;
#if CUDART_VERSION >= 12050
    cudaGetDriverEntryPointByVersion("cuTensorMapEncodeTiled", &fn, 12000,
                                     cudaEnableDefault, &qres);
#else
    cudaGetDriverEntryPoint("cuTensorMapEncodeTiled", &fn,
                            cudaEnableDefault, &qres);
#endif
    if (qres != cudaDriverEntryPointSuccess) return nullptr;
    return (PFN_encodeTiled)fn;
}

static bool make_map(PFN_encodeTiled enc, CUtensorMap* tm, void* base,
                     uint64_t d0, uint64_t d1, uint32_t b0, uint32_t b1)
{
    cuuint64_t dims[2]    = {d0, d1};
    cuuint64_t strides[1] = {d0 * 4};
    cuuint32_t box[2]     = {b0, b1};
    cuuint32_t es[2]      = {1, 1};
    CUresult r = enc(tm, CU_TENSOR_MAP_DATA_TYPE_FLOAT32, 2, base,
                     dims, strides, box, es,
                     CU_TENSOR_MAP_INTERLEAVE_NONE, CU_TENSOR_MAP_SWIZZLE_128B,
                     CU_TENSOR_MAP_L2_PROMOTION_L2_128B,
                     CU_TENSOR_MAP_FLOAT_OOB_FILL_NONE);
    return r == CUDA_SUCCESS;
}

// =====================================================================
// launch
// =====================================================================
extern "C" void kernel_launch(void* const* d_in, const int* in_sizes, int n_in,
                              void* d_out, int out_size)
{
    const float* x  = (const float*)d_in[0];
    const float* Wr = (const float*)d_in[1];
    const float* br = (const float*)d_in[2];
    const float* We = (const float*)d_in[3];
    const float* be = (const float*)d_in[4];
    float* out = (float*)d_out;

    const int T  = in_sizes[0] / H_DIM;   // 32768
    const int NB = T / 256;

    router_kernel<<<T / 32, 256>>>(x, Wr, br, T);
    transpose_round_kernel<<<dim3(H_DIM / 32, H_DIM / 32), dim3(32, 32)>>>(We);
    hist_kernel<<<NB, 256>>>(T);
    offsets_kernel<<<1, 256>>>(NB);
    scatter_kernel<<<NB, 256>>>(T);
    // NOTE: gather kernel eliminated — GEMM reads natural-order g_A and
    // row-scatters outputs via g_inv.

    cudaFuncAttributes attr;
    attr.numRegs = 0;
    cudaFuncGetAttributes(&attr, (const void*)gemm_tc_kernel);

    bool tc_ok = (attr.numRegs > 32);
    CUtensorMap tmA, tmB;
    if (tc_ok) {
        PFN_encodeTiled enc = get_encode_fn();
        void *pA = nullptr, *pW = nullptr;
        tc_ok = enc != nullptr
             && cudaGetSymbolAddress(&pA, g_A)  == cudaSuccess
             && cudaGetSymbolAddress(&pW, g_Wt) == cudaSuccess
             && make_map(enc, &tmA, pA, H_DIM, (uint64_t)T, GBK, 128)   // A half box 32x128
             && make_map(enc, &tmB, pW, H_DIM, H_DIM,       GBK, 128);  // B half box 32x128
    }

    if (tc_ok) {
        cudaFuncSetAttribute(gemm_tc_kernel,
                             cudaFuncAttributeMaxDynamicSharedMemorySize, GEMM_SMEM);
        dim3 gtc(2 * (H_DIM / GBN), T / GBM);   // (4, 128); x pairs = clusters of 2
        gemm_tc_kernel<<<gtc, 256, GEMM_SMEM>>>(tmA, tmB, be, out);
    } else {
        cudaFuncSetAttribute(gemm_wmma_kernel,
                             cudaFuncAttributeMaxDynamicSharedMemorySize, FB_SMEM);
        dim3 gfb(H_DIM / FBN, T / FBM);   // (8, 256)
        gemm_wmma_kernel<<<gfb, 256, FB_SMEM>>>(be, out);
    }
}

// round 10
// speedup vs baseline: 1.2002x; 1.0274x over previous
#include <cuda_runtime.h>
#include <cuda.h>
#include <mma.h>
#include <cstdint>

using namespace nvcuda;

#define T_MAX 32768
#define H_DIM 1024
#define E_DIM 8

// tcgen05 is only legal in arch-accelerated (sm_10xa) compilation passes.
#if defined(__CUDA_ARCH_FEAT_SM103_ALL) || defined(__CUDA_ARCH_FEAT_SM100_ALL) || defined(__CUDA_ARCH_FEAT_SM101_ALL)
#define HAS_TCGEN05 1
#else
#define HAS_TCGEN05 0
#endif

// ---------------- scratch (no runtime allocations allowed) ----------------
__device__ int   g_best [T_MAX];
__device__ float g_bestp[T_MAX];
__device__ int   g_order[T_MAX];
__device__ int   g_inv  [T_MAX];        // inv_order: source row s -> output row t
#define NB_MAX (T_MAX / 256)
__device__ int g_hist[NB_MAX * E_DIM];
__device__ int g_boff[NB_MAX * E_DIM];
__device__ float g_A [T_MAX * H_DIM];   // NATURAL-order x, RN-rounded to tf32
__device__ float g_Wt[H_DIM * H_DIM];   // W_expert transposed ([N,K]) + RN tf32

// ---------------- generic helpers ----------------
__device__ __forceinline__ uint32_t smem_u32(const void* p) {
    uint32_t a;
    asm("{ .reg .u64 t; cvta.to.shared.u64 t, %1; cvt.u32.u64 %0, t; }" : "=r"(a) : "l"(p));
    return a;
}
__device__ __forceinline__ float round_tf32(float v) {
    uint32_t o;
    asm("cvt.rna.tf32.f32 %0, %1;" : "=r"(o) : "f"(v));
    return __uint_as_float(o);
}
__device__ __forceinline__ void cp16(uint32_t saddr, const void* g) {
    asm volatile("cp.async.cg.shared.global [%0], [%1], 16;\n" :: "r"(saddr), "l"(g));
}
__device__ __forceinline__ void cp_commit() { asm volatile("cp.async.commit_group;\n"); }
template <int N> __device__ __forceinline__ void cp_wait() {
    asm volatile("cp.async.wait_group %0;\n" :: "n"(N));
}

__device__ __forceinline__ uint32_t elect_one_pred() {
    uint32_t pred;
    asm volatile(
        "{\n\t.reg .pred p;\n\t"
        "elect.sync _|p, 0xFFFFFFFF;\n\t"
        "selp.b32 %0, 1, 0, p;\n\t}"
        : "=r"(pred));
    return pred;
}

// =====================================================================
// Kernel 1: router — logits math UNCHANGED (defines the permutation);
// also stores RN-tf32-rounded x into g_A
// =====================================================================
__global__ __launch_bounds__(256) void router_kernel(
    const float* __restrict__ x, const float* __restrict__ Wr,
    const float* __restrict__ br, int T)
{
    __shared__ float sW[E_DIM][H_DIM];
    for (int i = threadIdx.x; i < H_DIM * E_DIM; i += 256) {
        int h = i >> 3, e = i & 7;
        sW[e][h] = Wr[i];
    }
    __syncthreads();

    int warp = threadIdx.x >> 5;
    int lane = threadIdx.x & 31;
    int tokBase = blockIdx.x * 32 + warp * 4;

    for (int tt = 0; tt < 4; ++tt) {
        int t = tokBase + tt;
        if (t >= T) break;
        const float* xr = x + (size_t)t * H_DIM;
        float*       ar = g_A + (size_t)t * H_DIM;

        float acc[E_DIM];
        #pragma unroll
        for (int e = 0; e < E_DIM; ++e) acc[e] = 0.f;
        #pragma unroll 4
        for (int i = 0; i < H_DIM / 32; ++i) {
            float xv = xr[i * 32 + lane];
            ar[i * 32 + lane] = round_tf32(xv);
            #pragma unroll
            for (int e = 0; e < E_DIM; ++e) acc[e] += xv * sW[e][i * 32 + lane];
        }
        #pragma unroll
        for (int e = 0; e < E_DIM; ++e) {
            #pragma unroll
            for (int off = 16; off; off >>= 1)
                acc[e] += __shfl_down_sync(0xffffffffu, acc[e], off);
        }
        if (lane == 0) {
            float l[E_DIM];
            #pragma unroll
            for (int e = 0; e < E_DIM; ++e) l[e] = acc[e] + br[e];
            int bi = 0; float bm = l[0];
            #pragma unroll
            for (int e = 1; e < E_DIM; ++e)
                if (l[e] > bm) { bm = l[e]; bi = e; }
            float s = 0.f;
            #pragma unroll
            for (int e = 0; e < E_DIM; ++e) s += expf(l[e] - bm);
            g_best [t] = bi;
            g_bestp[t] = 1.0f / s;
        }
    }
}

// =====================================================================
// Kernels 2-4: stable counting sort
// =====================================================================
__global__ void hist_kernel(int T)
{
    __shared__ int sh[E_DIM];
    if (threadIdx.x < E_DIM) sh[threadIdx.x] = 0;
    __syncthreads();
    int t = blockIdx.x * 256 + threadIdx.x;
    if (t < T) atomicAdd(&sh[g_best[t]], 1);
    __syncthreads();
    if (threadIdx.x < E_DIM)
        g_hist[blockIdx.x * E_DIM + threadIdx.x] = sh[threadIdx.x];
}

__global__ __launch_bounds__(256) void offsets_kernel(int NB)
{
    __shared__ int sh[NB_MAX * E_DIM];
    __shared__ int tot[E_DIM];
    __shared__ int base[E_DIM];
    const int tid = threadIdx.x;
    for (int i = tid; i < NB * E_DIM; i += 256) sh[i] = g_hist[i];
    __syncthreads();

    const int w = tid >> 5, l = tid & 31;
    if (w < E_DIM) {
        int run = 0;
        for (int c = 0; c < NB; c += 32) {
            int v = sh[(c + l) * E_DIM + w];
            int xs = v;
            #pragma unroll
            for (int off = 1; off < 32; off <<= 1) {
                int y = __shfl_up_sync(0xffffffffu, xs, off);
                if (l >= off) xs += y;
            }
            sh[(c + l) * E_DIM + w] = xs - v + run;
            run += __shfl_sync(0xffffffffu, xs, 31);
        }
        if (l == 0) tot[w] = run;
    }
    __syncthreads();
    if (tid == 0) {
        int b = 0;
        #pragma unroll
        for (int e = 0; e < E_DIM; ++e) { base[e] = b; b += tot[e]; }
    }
    __syncthreads();
    for (int i = tid; i < NB * E_DIM; i += 256)
        g_boff[i] = sh[i] + base[i & (E_DIM - 1)];
}

__global__ void scatter_kernel(int T)
{
    __shared__ int sb[256];
    int i = threadIdx.x;
    int t = blockIdx.x * 256 + i;
    sb[i] = (t < T) ? g_best[t] : -1;
    __syncthreads();
    if (t < T) {
        int e = sb[i];
        int rank = 0;
        for (int j = 0; j < i; ++j) rank += (sb[j] == e);
        int pos = g_boff[blockIdx.x * E_DIM + e] + rank;
        g_order[pos] = t;
        g_inv[t]     = pos;
    }
}

// =====================================================================
// Kernel 5: transpose W_expert -> [N,K] with RN tf32 rounding
// =====================================================================
__global__ void transpose_round_kernel(const float* __restrict__ We)
{
    __shared__ float tile[32][33];
    int n = blockIdx.x * 32 + threadIdx.x;
    int k = blockIdx.y * 32 + threadIdx.y;
    tile[threadIdx.y][threadIdx.x] = round_tf32(We[(size_t)k * H_DIM + n]);
    __syncthreads();
    int on = blockIdx.x * 32 + threadIdx.y;
    int ok = blockIdx.y * 32 + threadIdx.x;
    g_Wt[(size_t)on * H_DIM + ok] = tile[threadIdx.x][threadIdx.y];
}

// =====================================================================
// tcgen05-only machinery
// =====================================================================
#if HAS_TCGEN05

#define MBARRIER_INIT(addr, cnt) \
    asm volatile("mbarrier.init.shared.b64 [%0], %1;" :: "r"((uint32_t)(addr)), "r"((uint32_t)(cnt)) : "memory")
#define MBARRIER_INVAL(addr) \
    asm volatile("mbarrier.inval.shared.b64 [%0];" :: "r"((uint32_t)(addr)) : "memory")
#define MBARRIER_EXPECT_TX(addr, bytes) \
    asm volatile("mbarrier.arrive.expect_tx.shared.b64 _, [%0], %1;" \
                 :: "r"((uint32_t)(addr)), "r"((uint32_t)(bytes)) : "memory")
#define MBARRIER_WAIT_PARITY(mbar, parity) do {                                   \
    asm volatile(                                                                 \
        "{\n\t.reg .pred P1;\n\t"                                                 \
        "WAIT_LOOP_%=:\n\t"                                                       \
        "mbarrier.try_wait.parity.acquire.cta.shared::cta.b64 P1, [%0], %1, 0x989680;\n\t" \
        "@P1 bra.uni WAIT_DONE_%=;\n\t"                                           \
        "bra.uni WAIT_LOOP_%=;\n\t"                                               \
        "WAIT_DONE_%=:\n\t}"                                                      \
        :: "r"((uint32_t)(mbar)), "r"((uint32_t)(parity)) : "memory");            \
} while (0)

// arrive on the PAIR LEADER's mbarrier (clear bit 24 = Sm100MmaPeerBitMask)
#define MBARRIER_ARRIVE_LEADER(addr)                                      \
    asm volatile(                                                         \
        "{\n\t.reg .b32 lb;\n\t"                                          \
        "and.b32 lb, %0, 0xFEFFFFFF;\n\t"                                 \
        "mbarrier.arrive.shared::cluster.b64 _, [lb];\n\t}"               \
        :: "r"((uint32_t)(addr)) : "memory")

#define CLUSTER_SYNC() do {                                              \
    asm volatile("barrier.cluster.arrive.aligned;" ::: "memory");        \
    asm volatile("barrier.cluster.wait.aligned;" ::: "memory");          \
} while (0)

#define TCGEN05_ALLOC_CG2(sres, n) \
    asm volatile("tcgen05.alloc.cta_group::2.sync.aligned.shared::cta.b32 [%0], %1;" \
                 :: "r"((uint32_t)(sres)), "r"((uint32_t)(n)) : "memory")
#define TCGEN05_DEALLOC_CG2(tm, n) \
    asm volatile("tcgen05.dealloc.cta_group::2.sync.aligned.b32 %0, %1;" :: "r"(tm), "r"((uint32_t)(n)))
#define TCGEN05_RELINQ_CG2() \
    asm volatile("tcgen05.relinquish_alloc_permit.cta_group::2.sync.aligned;")
#define TCGEN05_COMMIT_MC_CG2(mbar, mask) \
    asm volatile("tcgen05.commit.cta_group::2.mbarrier::arrive::one.shared::cluster.multicast::cluster.b64 [%0], %1;" \
                 :: "r"((uint32_t)(mbar)), "h"((uint16_t)(mask)) : "memory")
#define TCGEN05_FENCE_AFTER()  asm volatile("tcgen05.fence::after_thread_sync;" ::: "memory")
#define TCGEN05_FENCE_BEFORE() asm volatile("tcgen05.fence::before_thread_sync;" ::: "memory")
#define TCGEN05_WAIT_LD()      asm volatile("tcgen05.wait::ld.sync.aligned;" ::: "memory")

// cg2 TMA: both CTAs execute; complete_tx routes to the LEADER's barrier.
#define TMA_LOAD_2D_CG2(smem_addr, tmap, cx, cy, mbar)                            \
    asm volatile(                                                                 \
        "{\n\t.reg .b32 lb;\n\t"                                                  \
        "and.b32 lb, %4, 0xFEFFFFFF;\n\t"                                         \
        "cp.async.bulk.tensor.2d.cta_group::2.shared::cluster.global.tile.mbarrier::complete_tx::bytes " \
        "[%0], [%1, {%2, %3}], [lb];\n\t}"                                        \
        :: "r"((uint32_t)(smem_addr)), "l"(tmap), "r"((int32_t)(cx)),             \
           "r"((int32_t)(cy)), "r"((uint32_t)(mbar)) : "memory")

#define TCGEN05_LD_32X32B_X32(r, tmem_addr)                                     \
    asm volatile(                                                               \
        "tcgen05.ld.sync.aligned.32x32b.x32.b32 "                               \
        "{%0, %1, %2, %3, %4, %5, %6, %7, "                                     \
        " %8, %9, %10, %11, %12, %13, %14, %15, "                               \
        " %16, %17, %18, %19, %20, %21, %22, %23, "                             \
        " %24, %25, %26, %27, %28, %29, %30, %31}, [%32];"                      \
        : "=r"((r)[0]),  "=r"((r)[1]),  "=r"((r)[2]),  "=r"((r)[3]),            \
          "=r"((r)[4]),  "=r"((r)[5]),  "=r"((r)[6]),  "=r"((r)[7]),            \
          "=r"((r)[8]),  "=r"((r)[9]),  "=r"((r)[10]), "=r"((r)[11]),           \
          "=r"((r)[12]), "=r"((r)[13]), "=r"((r)[14]), "=r"((r)[15]),           \
          "=r"((r)[16]), "=r"((r)[17]), "=r"((r)[18]), "=r"((r)[19]),           \
          "=r"((r)[20]), "=r"((r)[21]), "=r"((r)[22]), "=r"((r)[23]),           \
          "=r"((r)[24]), "=r"((r)[25]), "=r"((r)[26]), "=r"((r)[27]),           \
          "=r"((r)[28]), "=r"((r)[29]), "=r"((r)[30]), "=r"((r)[31])            \
        : "r"(tmem_addr))

static constexpr uint64_t SMEM_DESC_BASE_SW128 =
    (uint64_t(2)  << 61) | (uint64_t(1) << 46) | (uint64_t(64) << 32) | (uint64_t(1) << 16);
#define MAKE_SMEM_DESC(base) (SMEM_DESC_BASE_SW128 | ((uint64_t)((base) >> 4) & 0x3FFF))

// idesc kind::tf32, cg2: d=F32, a/b=TF32, N=256, M=256 -> 0x10400910
#define GEMM_IDESC_CG2 0x10400910u

__device__ __forceinline__ void mma_tf32_ss_cg2(uint32_t d, uint64_t a, uint64_t b, uint32_t en) {
    asm volatile(
        "{\n\t.reg .pred p;\n\t"
        "setp.ne.u32 p, %4, 0;\n\t"
        "tcgen05.mma.cta_group::2.kind::tf32 [%0], %1, %2, %3, "
        "{%5, %5, %5, %5, %5, %5, %5, %5}, p;\n\t}"
        :: "r"(d), "l"(a), "l"(b), "r"(GEMM_IDESC_CG2), "r"(en), "r"(0u) : "memory");
}
#endif  // HAS_TCGEN05

// =====================================================================
// Kernel 6a: PERSISTENT tcgen05 tf32 cg2 pair-GEMM. 74 resident clusters
// loop over 256 tiles (M=256 x N=512). TMEM alloc/mbarriers/cluster syncs
// once per kernel; ring phases persist across tiles; EPI barrier guards
// TMEM reuse between tile i epilogue and tile i+1 MMAs.
// =====================================================================
#define GBM 256
#define GBN 512
#define GBK 32
#define A_ST 16384
#define B_ST 16384
#define STAGE_BYTES (A_ST + 2 * B_ST)   // 49152 B
#define NSTAGES 4
#define GEMM_SMEM (4096 + NSTAGES * STAGE_BYTES)   // 200704 B
#define NCLUSTERS 74
#define GEMM_GRID  (2 * NCLUSTERS)

// ctrl: 0 tmem ptr; full(s)=8+16s; empty(s)=16+16s; done=72; epi=80
#define MB_FULL(s)  (sb + 8  + (s) * 16)
#define MB_EMPTY(s) (sb + 16 + (s) * 16)
#define MB_DONE     (sb + 72)
#define MB_EPI      (sb + 80)

__global__ __launch_bounds__(256)
#if HAS_TCGEN05
__cluster_dims__(2, 1, 1)
#endif
void gemm_tc_kernel(const __grid_constant__ CUtensorMap tmA,
                    const __grid_constant__ CUtensorMap tmB,
                    const float* __restrict__ be, float* __restrict__ out,
                    int nTiles)
{
#if HAS_TCGEN05
    extern __shared__ char smem[];
    uint32_t sb = smem_u32(smem);
    const int tid  = threadIdx.x;
    const int wid  = tid >> 5;
    const int lane = tid & 31;
    uint32_t rank;
    asm("mov.u32 %0, %%cluster_ctarank;" : "=r"(rank));
    const int clusterId = blockIdx.x >> 1;

    float* sBias = (float*)(smem + 128);    // 512 f32
    float* sBp   = (float*)(smem + 2176);   // 128 f32
    int*   sTo   = (int*)  (smem + 2688);   // 128 i32
    const uint32_t buf0 = sb + 4096;

    if (wid == 0) TCGEN05_ALLOC_CG2(sb + 0, 512);
    if (tid == 0) {
        #pragma unroll
        for (int s = 0; s < NSTAGES; ++s) {
            MBARRIER_INIT(MB_FULL(s), 1);
            MBARRIER_INIT(MB_EMPTY(s), 1);
        }
        MBARRIER_INIT(MB_DONE, 1);
        MBARRIER_INIT(MB_EPI, 2);   // one arrive per CTA of the pair
    }
    __syncthreads();
    CLUSTER_SYNC();
    uint32_t tmem;
    asm volatile("ld.shared.b32 %0, [%1];" : "=r"(tmem) : "r"(sb + 0));

    const int NST = H_DIM / GBK;   // 32

    // persistent cursors (live in role threads' registers across tiles)
    int phE[NSTAGES] = {1, 1, 1, 1};
    int phF[NSTAGES] = {0, 0, 0, 0};
    int slotP = 0, slotC = 0;
    int donePh = 0, epiPh = 0;
    int firstTile = 1;

    for (int ti = clusterId; ti < nTiles; ti += NCLUSTERS) {
        const int rowBase = (ti >> 1) * GBM;
        const int colBase = (ti & 1) * GBN;

        if (wid == 1 && elect_one_pred()) {
            // ---- producer: own A half + own halves of both B blocks ----
            for (int kt = 0; kt < NST; ++kt) {
                const int s = slotP;
                MBARRIER_WAIT_PARITY(MB_EMPTY(s), phE[s]); phE[s] ^= 1;
                const uint32_t ab = buf0 + s * STAGE_BYTES;
                if (rank == 0) MBARRIER_EXPECT_TX(MB_FULL(s), 2 * STAGE_BYTES);
                TMA_LOAD_2D_CG2(ab,               &tmA, kt * GBK,
                                rowBase + (int)rank * 128, MB_FULL(s));
                TMA_LOAD_2D_CG2(ab + A_ST,        &tmB, kt * GBK,
                                colBase + (int)rank * 128, MB_FULL(s));
                TMA_LOAD_2D_CG2(ab + A_ST + B_ST, &tmB, kt * GBK,
                                colBase + 256 + (int)rank * 128, MB_FULL(s));
                slotP = (slotP + 1) & (NSTAGES - 1);
            }
        }
        if (rank == 0 && wid == 0 && elect_one_pred()) {
            // ---- leader MMA: TMEM free only after both epilogues of prev tile ----
            if (!firstTile) { MBARRIER_WAIT_PARITY(MB_EPI, epiPh); epiPh ^= 1; }
            for (int kt = 0; kt < NST; ++kt) {
                const int s = slotC;
                MBARRIER_WAIT_PARITY(MB_FULL(s), phF[s]); phF[s] ^= 1;
                const uint32_t ab = buf0 + s * STAGE_BYTES;
                uint64_t ad  = MAKE_SMEM_DESC(ab);
                uint64_t bd0 = MAKE_SMEM_DESC(ab + A_ST);
                uint64_t bd1 = MAKE_SMEM_DESC(ab + A_ST + B_ST);
                #pragma unroll
                for (int ks = 0; ks < 4; ++ks) {
                    uint32_t en = (kt | ks) != 0;
                    mma_tf32_ss_cg2(tmem,       ad + ks * 2, bd0 + ks * 2, en);
                    mma_tf32_ss_cg2(tmem + 256, ad + ks * 2, bd1 + ks * 2, en);
                }
                TCGEN05_COMMIT_MC_CG2(MB_EMPTY(s), 0x3);
                slotC = (slotC + 1) & (NSTAGES - 1);
            }
            TCGEN05_COMMIT_MC_CG2(MB_DONE, 0x3);
        }

        // ---- per-tile epilogue staging (all threads) ----
        sBias[tid]       = be[colBase + tid];
        sBias[tid + 256] = be[colBase + 256 + tid];
        if (tid < 128) {
            int srow = rowBase + (int)rank * 128 + tid;
            int trow = g_inv[srow];
            sTo[tid] = trow;
            sBp[tid] = g_bestp[trow];
        }

        MBARRIER_WAIT_PARITY(MB_DONE, donePh); donePh ^= 1;
        TCGEN05_FENCE_AFTER();
        __syncthreads();   // staging visible + everyone past DONE

        {
            const int sub    = wid & 3;
            const int half   = wid >> 2;
            const int rowLoc = sub * 32 + lane;
            const float p = sBp[rowLoc];
            const uint32_t dbase = tmem + half * 256;
            float* orow = out + (size_t)sTo[rowLoc] * H_DIM + colBase + half * 256;
            #pragma unroll
            for (int ch = 0; ch < 8; ++ch) {
                uint32_t r[32];
                TCGEN05_LD_32X32B_X32(r, dbase + ch * 32);
                TCGEN05_WAIT_LD();
                #pragma unroll
                for (int i = 0; i < 32; i += 4) {
                    const int c = half * 256 + ch * 32 + i;
                    float4 v;
                    v.x = (__uint_as_float(r[i + 0]) + sBias[c + 0]) * p;
                    v.y = (__uint_as_float(r[i + 1]) + sBias[c + 1]) * p;
                    v.z = (__uint_as_float(r[i + 2]) + sBias[c + 2]) * p;
                    v.w = (__uint_as_float(r[i + 3]) + sBias[c + 3]) * p;
                    *(float4*)(orow + ch * 32 + i) = v;
                }
            }
            TCGEN05_FENCE_BEFORE();
        }
        __syncthreads();   // all reads of TMEM + staging done
        if (tid == 0) MBARRIER_ARRIVE_LEADER(MB_EPI);   // both CTAs -> leader
        firstTile = 0;
    }

    // ---- teardown (once) ----
    __syncthreads();
    CLUSTER_SYNC();
    if (tid == 0) {
        #pragma unroll
        for (int s = 0; s < NSTAGES; ++s) {
            MBARRIER_INVAL(MB_FULL(s));
            MBARRIER_INVAL(MB_EMPTY(s));
        }
        MBARRIER_INVAL(MB_DONE);
        MBARRIER_INVAL(MB_EPI);
    }
    __syncthreads();
    if (wid == 0) {
        TCGEN05_RELINQ_CG2();
        TCGEN05_DEALLOC_CG2(tmem, 512);
    }
    CLUSTER_SYNC();
#endif  // HAS_TCGEN05
}

// =====================================================================
// Kernel 6b: WMMA tf32 fallback 128x128 (ALL passes) — natural-order A,
// row-scatter epilogue via g_inv.
// =====================================================================
#define FBM 128
#define FBN 128
#define FBK 16
#define FLD 20
#define FNKT (H_DIM / FBK)
#define FB_SMEM (( (2*FBM*FLD) + (2*FBN*FLD) + 8*256 + FBM + FBN + FBM ) * 4)

__global__ __launch_bounds__(256) void gemm_wmma_kernel(
    const float* __restrict__ be, float* __restrict__ out)
{
    extern __shared__ float fsm[];
    float* As    = fsm;
    float* Bs    = As + 2 * FBM * FLD;
    float* sC    = Bs + 2 * FBN * FLD;
    float* sBias = sC + 8 * 256;
    float* sBp   = sBias + FBN;
    int*   sTo   = (int*)(sBp + FBM);

    const int tid = threadIdx.x;
    const int rowBase = blockIdx.y * FBM;
    const int colBase = blockIdx.x * FBN;

    if (tid < FBM) {
        int trow = g_inv[rowBase + tid];
        sTo[tid] = trow;
        sBp[tid] = g_bestp[trow];
    } else {
        sBias[tid - FBM] = be[colBase + tid - FBM];
    }

    const int arow = tid >> 1;
    const int aseg = (tid & 1) * 8;
    const float* aSrc = g_A  + (size_t)(rowBase + arow) * H_DIM + aseg;
    const float* bSrc = g_Wt + (size_t)(colBase + arow) * H_DIM + aseg;
    const uint32_t asm_base = smem_u32(As);
    const uint32_t bsm_base = smem_u32(Bs);

    auto load_tiles = [&](int buf, int kt) {
        const int k0 = kt * FBK;
        uint32_t ao = asm_base + (buf * FBM * FLD + arow * FLD + aseg) * 4;
        uint32_t bo = bsm_base + (buf * FBN * FLD + arow * FLD + aseg) * 4;
        cp16(ao,      aSrc + k0);
        cp16(ao + 16, aSrc + k0 + 4);
        cp16(bo,      bSrc + k0);
        cp16(bo + 16, bSrc + k0 + 4);
    };

    const int warpId = tid >> 5;
    const int wm = warpId >> 2;
    const int wn = warpId & 3;

    wmma::fragment<wmma::accumulator, 16, 16, 8, float> acc[4][2];
    #pragma unroll
    for (int mi = 0; mi < 4; ++mi)
        #pragma unroll
        for (int ni = 0; ni < 2; ++ni)
            wmma::fill_fragment(acc[mi][ni], 0.0f);

    load_tiles(0, 0);
    cp_commit();

    for (int kt = 0; kt < FNKT; ++kt) {
        if (kt + 1 < FNKT) {
            load_tiles((kt + 1) & 1, kt + 1);
            cp_commit();
            cp_wait<1>();
        } else {
            cp_wait<0>();
        }
        __syncthreads();

        const int buf = kt & 1;
        #pragma unroll
        for (int ks = 0; ks < 2; ++ks) {
            wmma::fragment<wmma::matrix_a, 16, 16, 8, wmma::precision::tf32,
                           wmma::row_major> af[4];
            wmma::fragment<wmma::matrix_b, 16, 16, 8, wmma::precision::tf32,
                           wmma::col_major> bf[2];
            #pragma unroll
            for (int mi = 0; mi < 4; ++mi)
                wmma::load_matrix_sync(
                    af[mi], &As[buf * FBM * FLD + (wm * 64 + mi * 16) * FLD + ks * 8], FLD);
            #pragma unroll
            for (int ni = 0; ni < 2; ++ni)
                wmma::load_matrix_sync(
                    bf[ni], &Bs[buf * FBN * FLD + (wn * 32 + ni * 16) * FLD + ks * 8], FLD);
            #pragma unroll
            for (int mi = 0; mi < 4; ++mi)
                #pragma unroll
                for (int ni = 0; ni < 2; ++ni)
                    wmma::mma_sync(acc[mi][ni], af[mi], bf[ni], acc[mi][ni]);
        }
        __syncthreads();
    }

    const int lane = tid & 31;
    float* stg = &sC[warpId * 256];
    #pragma unroll
    for (int mi = 0; mi < 4; ++mi) {
        #pragma unroll
        for (int ni = 0; ni < 2; ++ni) {
            wmma::store_matrix_sync(stg, acc[mi][ni], 16, wmma::mem_row_major);
            __syncwarp();
            const int r = lane >> 1;
            const int c = (lane & 1) * 8;
            const int rowL = wm * 64 + mi * 16 + r;
            const int colL = wn * 32 + ni * 16 + c;
            const float p = sBp[rowL];
            float4 v0 = *(const float4*)&stg[r * 16 + c];
            float4 v1 = *(const float4*)&stg[r * 16 + c + 4];
            float4 o0, o1;
            o0.x = (v0.x + sBias[colL + 0]) * p;
            o0.y = (v0.y + sBias[colL + 1]) * p;
            o0.z = (v0.z + sBias[colL + 2]) * p;
            o0.w = (v0.w + sBias[colL + 3]) * p;
            o1.x = (v1.x + sBias[colL + 4]) * p;
            o1.y = (v1.y + sBias[colL + 5]) * p;
            o1.z = (v1.z + sBias[colL + 6]) * p;
            o1.w = (v1.w + sBias[colL + 7]) * p;
            float* dst = out + (size_t)sTo[rowL] * H_DIM + colBase + colL;
            *(float4*)(dst + 0) = o0;
            *(float4*)(dst + 4) = o1;
            __syncwarp();
        }
    }
}

// =====================================================================
// host: tensor-map construction via driver entry point (no -lcuda link)
// =====================================================================
typedef CUresult (*PFN_encodeTiled)(
    CUtensorMap*, CUtensorMapDataType, cuuint32_t, void*,
    const cuuint64_t*, const cuuint64_t*, const cuuint32_t*, const cuuint32_t*,
    CUtensorMapInterleave, CUtensorMapSwizzle, CUtensorMapL2promotion,
    CUtensorMapFloatOOBfill);

static PFN_encodeTiled get_encode_fn()
{
    void* fn = nullptr;
    cudaDriverEntryPointQueryResult qres = cudaDriverEntryPointSymbolNotFound;
#if CUDART_VERSION >= 12050
    cudaGetDriverEntryPointByVersion("cuTensorMapEncodeTiled", &fn, 12000,
                                     cudaEnableDefault, &qres);
#else
    cudaGetDriverEntryPoint("cuTensorMapEncodeTiled", &fn,
                            cudaEnableDefault, &qres);
#endif
    if (qres != cudaDriverEntryPointSuccess) return nullptr;
    return (PFN_encodeTiled)fn;
}

static bool make_map(PFN_encodeTiled enc, CUtensorMap* tm, void* base,
                     uint64_t d0, uint64_t d1, uint32_t b0, uint32_t b1)
{
    cuuint64_t dims[2]    = {d0, d1};
    cuuint64_t strides[1] = {d0 * 4};
    cuuint32_t box[2]     = {b0, b1};
    cuuint32_t es[2]      = {1, 1};
    CUresult r = enc(tm, CU_TENSOR_MAP_DATA_TYPE_FLOAT32, 2, base,
                     dims, strides, box, es,
                     CU_TENSOR_MAP_INTERLEAVE_NONE, CU_TENSOR_MAP_SWIZZLE_128B,
                     CU_TENSOR_MAP_L2_PROMOTION_L2_128B,
                     CU_TENSOR_MAP_FLOAT_OOB_FILL_NONE);
    return r == CUDA_SUCCESS;
}

// =====================================================================
// launch
// =====================================================================
extern "C" void kernel_launch(void* const* d_in, const int* in_sizes, int n_in,
                              void* d_out, int out_size)
{
    const float* x  = (const float*)d_in[0];
    const float* Wr = (const float*)d_in[1];
    const float* br = (const float*)d_in[2];
    const float* We = (const float*)d_in[3];
    const float* be = (const float*)d_in[4];
    float* out = (float*)d_out;

    const int T  = in_sizes[0] / H_DIM;   // 32768
    const int NB = T / 256;

    router_kernel<<<T / 32, 256>>>(x, Wr, br, T);
    transpose_round_kernel<<<dim3(H_DIM / 32, H_DIM / 32), dim3(32, 32)>>>(We);
    hist_kernel<<<NB, 256>>>(T);
    offsets_kernel<<<1, 256>>>(NB);
    scatter_kernel<<<NB, 256>>>(T);

    cudaFuncAttributes attr;
    attr.numRegs = 0;
    cudaFuncGetAttributes(&attr, (const void*)gemm_tc_kernel);

    bool tc_ok = (attr.numRegs > 32);
    CUtensorMap tmA, tmB;
    if (tc_ok) {
        PFN_encodeTiled enc = get_encode_fn();
        void *pA = nullptr, *pW = nullptr;
        tc_ok = enc != nullptr
             && cudaGetSymbolAddress(&pA, g_A)  == cudaSuccess
             && cudaGetSymbolAddress(&pW, g_Wt) == cudaSuccess
             && make_map(enc, &tmA, pA, H_DIM, (uint64_t)T, GBK, 128)
             && make_map(enc, &tmB, pW, H_DIM, H_DIM,       GBK, 128);
    }

    if (tc_ok) {
        cudaFuncSetAttribute(gemm_tc_kernel,
                             cudaFuncAttributeMaxDynamicSharedMemorySize, GEMM_SMEM);
        const int nTiles = (T / GBM) * (H_DIM / GBN);   // 256
        gemm_tc_kernel<<<GEMM_GRID, 256, GEMM_SMEM>>>(tmA, tmB, be, out, nTiles);
    } else {
        cudaFuncSetAttribute(gemm_wmma_kernel,
                             cudaFuncAttributeMaxDynamicSharedMemorySize, FB_SMEM);
        dim3 gfb(H_DIM / FBN, T / FBM);   // (8, 256)
        gemm_wmma_kernel<<<gfb, 256, FB_SMEM>>>(be, out);
    }
}

// round 11
// speedup vs baseline: 1.4318x; 1.1930x over previous
#include <cuda_runtime.h>
#include <cuda.h>
#include <cuda_fp16.h>
#include <mma.h>
#include <cstdint>

using namespace nvcuda;

#define T_MAX 32768
#define H_DIM 1024
#define E_DIM 8

// tcgen05 is only legal in arch-accelerated (sm_10xa) compilation passes.
#if defined(__CUDA_ARCH_FEAT_SM103_ALL) || defined(__CUDA_ARCH_FEAT_SM100_ALL) || defined(__CUDA_ARCH_FEAT_SM101_ALL)
#define HAS_TCGEN05 1
#else
#define HAS_TCGEN05 0
#endif

// ---------------- scratch (no runtime allocations allowed) ----------------
__device__ int   g_best [T_MAX];
__device__ float g_bestp[T_MAX];
__device__ int   g_order[T_MAX];
__device__ int   g_inv  [T_MAX];        // inv_order: source row s -> output row t
#define NB_MAX (T_MAX / 256)
__device__ int g_hist[NB_MAX * E_DIM];
__device__ int g_boff[NB_MAX * E_DIM];
__device__ __half g_A [T_MAX * H_DIM];  // NATURAL-order x, RN-rounded to fp16
__device__ __half g_Wt[H_DIM * H_DIM];  // W_expert transposed ([N,K]) + RN fp16

// ---------------- generic helpers ----------------
__device__ __forceinline__ uint32_t smem_u32(const void* p) {
    uint32_t a;
    asm("{ .reg .u64 t; cvta.to.shared.u64 t, %1; cvt.u32.u64 %0, t; }" : "=r"(a) : "l"(p));
    return a;
}
__device__ __forceinline__ void cp16(uint32_t saddr, const void* g) {
    asm volatile("cp.async.cg.shared.global [%0], [%1], 16;\n" :: "r"(saddr), "l"(g));
}
__device__ __forceinline__ void cp_commit() { asm volatile("cp.async.commit_group;\n"); }
template <int N> __device__ __forceinline__ void cp_wait() {
    asm volatile("cp.async.wait_group %0;\n" :: "n"(N));
}

__device__ __forceinline__ uint32_t elect_one_pred() {
    uint32_t pred;
    asm volatile(
        "{\n\t.reg .pred p;\n\t"
        "elect.sync _|p, 0xFFFFFFFF;\n\t"
        "selp.b32 %0, 1, 0, p;\n\t}"
        : "=r"(pred));
    return pred;
}

// =====================================================================
// Kernel 1: router — logits math UNCHANGED (defines the permutation);
// stores RN-fp16-rounded x into g_A (same mantissa width as tf32)
// =====================================================================
__global__ __launch_bounds__(256) void router_kernel(
    const float* __restrict__ x, const float* __restrict__ Wr,
    const float* __restrict__ br, int T)
{
    __shared__ float sW[E_DIM][H_DIM];
    for (int i = threadIdx.x; i < H_DIM * E_DIM; i += 256) {
        int h = i >> 3, e = i & 7;
        sW[e][h] = Wr[i];
    }
    __syncthreads();

    int warp = threadIdx.x >> 5;
    int lane = threadIdx.x & 31;
    int tokBase = blockIdx.x * 32 + warp * 4;

    for (int tt = 0; tt < 4; ++tt) {
        int t = tokBase + tt;
        if (t >= T) break;
        const float* xr = x + (size_t)t * H_DIM;
        __half*      ar = g_A + (size_t)t * H_DIM;

        float acc[E_DIM];
        #pragma unroll
        for (int e = 0; e < E_DIM; ++e) acc[e] = 0.f;
        #pragma unroll 4
        for (int i = 0; i < H_DIM / 32; ++i) {
            float xv = xr[i * 32 + lane];
            ar[i * 32 + lane] = __float2half_rn(xv);
            #pragma unroll
            for (int e = 0; e < E_DIM; ++e) acc[e] += xv * sW[e][i * 32 + lane];
        }
        #pragma unroll
        for (int e = 0; e < E_DIM; ++e) {
            #pragma unroll
            for (int off = 16; off; off >>= 1)
                acc[e] += __shfl_down_sync(0xffffffffu, acc[e], off);
        }
        if (lane == 0) {
            float l[E_DIM];
            #pragma unroll
            for (int e = 0; e < E_DIM; ++e) l[e] = acc[e] + br[e];
            int bi = 0; float bm = l[0];
            #pragma unroll
            for (int e = 1; e < E_DIM; ++e)
                if (l[e] > bm) { bm = l[e]; bi = e; }
            float s = 0.f;
            #pragma unroll
            for (int e = 0; e < E_DIM; ++e) s += expf(l[e] - bm);
            g_best [t] = bi;
            g_bestp[t] = 1.0f / s;
        }
    }
}

// =====================================================================
// Kernels 2-4: stable counting sort
// =====================================================================
__global__ void hist_kernel(int T)
{
    __shared__ int sh[E_DIM];
    if (threadIdx.x < E_DIM) sh[threadIdx.x] = 0;
    __syncthreads();
    int t = blockIdx.x * 256 + threadIdx.x;
    if (t < T) atomicAdd(&sh[g_best[t]], 1);
    __syncthreads();
    if (threadIdx.x < E_DIM)
        g_hist[blockIdx.x * E_DIM + threadIdx.x] = sh[threadIdx.x];
}

__global__ __launch_bounds__(256) void offsets_kernel(int NB)
{
    __shared__ int sh[NB_MAX * E_DIM];
    __shared__ int tot[E_DIM];
    __shared__ int base[E_DIM];
    const int tid = threadIdx.x;
    for (int i = tid; i < NB * E_DIM; i += 256) sh[i] = g_hist[i];
    __syncthreads();

    const int w = tid >> 5, l = tid & 31;
    if (w < E_DIM) {
        int run = 0;
        for (int c = 0; c < NB; c += 32) {
            int v = sh[(c + l) * E_DIM + w];
            int xs = v;
            #pragma unroll
            for (int off = 1; off < 32; off <<= 1) {
                int y = __shfl_up_sync(0xffffffffu, xs, off);
                if (l >= off) xs += y;
            }
            sh[(c + l) * E_DIM + w] = xs - v + run;
            run += __shfl_sync(0xffffffffu, xs, 31);
        }
        if (l == 0) tot[w] = run;
    }
    __syncthreads();
    if (tid == 0) {
        int b = 0;
        #pragma unroll
        for (int e = 0; e < E_DIM; ++e) { base[e] = b; b += tot[e]; }
    }
    __syncthreads();
    for (int i = tid; i < NB * E_DIM; i += 256)
        g_boff[i] = sh[i] + base[i & (E_DIM - 1)];
}

__global__ void scatter_kernel(int T)
{
    __shared__ int sb[256];
    int i = threadIdx.x;
    int t = blockIdx.x * 256 + i;
    sb[i] = (t < T) ? g_best[t] : -1;
    __syncthreads();
    if (t < T) {
        int e = sb[i];
        int rank = 0;
        for (int j = 0; j < i; ++j) rank += (sb[j] == e);
        int pos = g_boff[blockIdx.x * E_DIM + e] + rank;
        g_order[pos] = t;
        g_inv[t]     = pos;
    }
}

// =====================================================================
// Kernel 5: transpose W_expert -> [N,K] with RN fp16 rounding
// =====================================================================
__global__ void transpose_round_kernel(const float* __restrict__ We)
{
    __shared__ float tile[32][33];
    int n = blockIdx.x * 32 + threadIdx.x;
    int k = blockIdx.y * 32 + threadIdx.y;
    tile[threadIdx.y][threadIdx.x] = We[(size_t)k * H_DIM + n];
    __syncthreads();
    int on = blockIdx.x * 32 + threadIdx.y;
    int ok = blockIdx.y * 32 + threadIdx.x;
    g_Wt[(size_t)on * H_DIM + ok] = __float2half_rn(tile[threadIdx.x][threadIdx.y]);
}

// =====================================================================
// tcgen05-only machinery
// =====================================================================
#if HAS_TCGEN05

#define MBARRIER_INIT(addr, cnt) \
    asm volatile("mbarrier.init.shared.b64 [%0], %1;" :: "r"((uint32_t)(addr)), "r"((uint32_t)(cnt)) : "memory")
#define MBARRIER_INVAL(addr) \
    asm volatile("mbarrier.inval.shared.b64 [%0];" :: "r"((uint32_t)(addr)) : "memory")
#define MBARRIER_EXPECT_TX(addr, bytes) \
    asm volatile("mbarrier.arrive.expect_tx.shared.b64 _, [%0], %1;" \
                 :: "r"((uint32_t)(addr)), "r"((uint32_t)(bytes)) : "memory")
#define MBARRIER_WAIT_PARITY(mbar, parity) do {                                   \
    asm volatile(                                                                 \
        "{\n\t.reg .pred P1;\n\t"                                                 \
        "WAIT_LOOP_%=:\n\t"                                                       \
        "mbarrier.try_wait.parity.acquire.cta.shared::cta.b64 P1, [%0], %1, 0x989680;\n\t" \
        "@P1 bra.uni WAIT_DONE_%=;\n\t"                                           \
        "bra.uni WAIT_LOOP_%=;\n\t"                                               \
        "WAIT_DONE_%=:\n\t}"                                                      \
        :: "r"((uint32_t)(mbar)), "r"((uint32_t)(parity)) : "memory");            \
} while (0)

// arrive on the PAIR LEADER's mbarrier (clear bit 24 = Sm100MmaPeerBitMask)
#define MBARRIER_ARRIVE_LEADER(addr)                                      \
    asm volatile(                                                         \
        "{\n\t.reg .b32 lb;\n\t"                                          \
        "and.b32 lb, %0, 0xFEFFFFFF;\n\t"                                 \
        "mbarrier.arrive.shared::cluster.b64 _, [lb];\n\t}"               \
        :: "r"((uint32_t)(addr)) : "memory")

#define CLUSTER_SYNC() do {                                              \
    asm volatile("barrier.cluster.arrive.aligned;" ::: "memory");        \
    asm volatile("barrier.cluster.wait.aligned;" ::: "memory");          \
} while (0)

#define TCGEN05_ALLOC_CG2(sres, n) \
    asm volatile("tcgen05.alloc.cta_group::2.sync.aligned.shared::cta.b32 [%0], %1;" \
                 :: "r"((uint32_t)(sres)), "r"((uint32_t)(n)) : "memory")
#define TCGEN05_DEALLOC_CG2(tm, n) \
    asm volatile("tcgen05.dealloc.cta_group::2.sync.aligned.b32 %0, %1;" :: "r"(tm), "r"((uint32_t)(n)))
#define TCGEN05_RELINQ_CG2() \
    asm volatile("tcgen05.relinquish_alloc_permit.cta_group::2.sync.aligned;")
#define TCGEN05_COMMIT_MC_CG2(mbar, mask) \
    asm volatile("tcgen05.commit.cta_group::2.mbarrier::arrive::one.shared::cluster.multicast::cluster.b64 [%0], %1;" \
                 :: "r"((uint32_t)(mbar)), "h"((uint16_t)(mask)) : "memory")
#define TCGEN05_FENCE_AFTER()  asm volatile("tcgen05.fence::after_thread_sync;" ::: "memory")
#define TCGEN05_FENCE_BEFORE() asm volatile("tcgen05.fence::before_thread_sync;" ::: "memory")
#define TCGEN05_WAIT_LD()      asm volatile("tcgen05.wait::ld.sync.aligned;" ::: "memory")

// cg2 TMA: both CTAs execute; complete_tx routes to the LEADER's barrier.
#define TMA_LOAD_2D_CG2(smem_addr, tmap, cx, cy, mbar)                            \
    asm volatile(                                                                 \
        "{\n\t.reg .b32 lb;\n\t"                                                  \
        "and.b32 lb, %4, 0xFEFFFFFF;\n\t"                                         \
        "cp.async.bulk.tensor.2d.cta_group::2.shared::cluster.global.tile.mbarrier::complete_tx::bytes " \
        "[%0], [%1, {%2, %3}], [lb];\n\t}"                                        \
        :: "r"((uint32_t)(smem_addr)), "l"(tmap), "r"((int32_t)(cx)),             \
           "r"((int32_t)(cy)), "r"((uint32_t)(mbar)) : "memory")

#define TCGEN05_LD_32X32B_X32(r, tmem_addr)                                     \
    asm volatile(                                                               \
        "tcgen05.ld.sync.aligned.32x32b.x32.b32 "                               \
        "{%0, %1, %2, %3, %4, %5, %6, %7, "                                     \
        " %8, %9, %10, %11, %12, %13, %14, %15, "                               \
        " %16, %17, %18, %19, %20, %21, %22, %23, "                             \
        " %24, %25, %26, %27, %28, %29, %30, %31}, [%32];"                      \
        : "=r"((r)[0]),  "=r"((r)[1]),  "=r"((r)[2]),  "=r"((r)[3]),            \
          "=r"((r)[4]),  "=r"((r)[5]),  "=r"((r)[6]),  "=r"((r)[7]),            \
          "=r"((r)[8]),  "=r"((r)[9]),  "=r"((r)[10]), "=r"((r)[11]),           \
          "=r"((r)[12]), "=r"((r)[13]), "=r"((r)[14]), "=r"((r)[15]),           \
          "=r"((r)[16]), "=r"((r)[17]), "=r"((r)[18]), "=r"((r)[19]),           \
          "=r"((r)[20]), "=r"((r)[21]), "=r"((r)[22]), "=r"((r)[23]),           \
          "=r"((r)[24]), "=r"((r)[25]), "=r"((r)[26]), "=r"((r)[27]),           \
          "=r"((r)[28]), "=r"((r)[29]), "=r"((r)[30]), "=r"((r)[31])            \
        : "r"(tmem_addr))

static constexpr uint64_t SMEM_DESC_BASE_SW128 =
    (uint64_t(2)  << 61) | (uint64_t(1) << 46) | (uint64_t(64) << 32) | (uint64_t(1) << 16);
#define MAKE_SMEM_DESC(base) (SMEM_DESC_BASE_SW128 | ((uint64_t)((base) >> 4) & 0x3FFF))

// idesc kind::f16, cg2: d=F32(1<<4), atype=FP16(0), btype=FP16(0),
// (N=256/8)<<17, (M=256/16)<<24 -> 0x10400010
#define GEMM_IDESC_F16_CG2 0x10400010u

__device__ __forceinline__ void mma_f16_ss_cg2(uint32_t d, uint64_t a, uint64_t b, uint32_t en) {
    asm volatile(
        "{\n\t.reg .pred p;\n\t"
        "setp.ne.u32 p, %4, 0;\n\t"
        "tcgen05.mma.cta_group::2.kind::f16 [%0], %1, %2, %3, "
        "{%5, %5, %5, %5, %5, %5, %5, %5}, p;\n\t}"
        :: "r"(d), "l"(a), "l"(b), "r"(GEMM_IDESC_F16_CG2), "r"(en), "r"(0u) : "memory");
}
#endif  // HAS_TCGEN05

// =====================================================================
// Kernel 6a: PERSISTENT fp16 cg2 pair-GEMM. Same ring/protocol as the
// committed tf32 version; K-chunk 64 (same 128B SW128 rows, half bytes).
// =====================================================================
#define GBM 256
#define GBN 512
#define GBK 64                          // fp16: 64 elements = 128 B per row
#define A_ST 16384                      // 128 rows x 128 B
#define B_ST 16384
#define STAGE_BYTES (A_ST + 2 * B_ST)   // 49152 B
#define NSTAGES 4
#define GEMM_SMEM (4096 + NSTAGES * STAGE_BYTES)   // 200704 B
#define NCLUSTERS 74
#define GEMM_GRID  (2 * NCLUSTERS)

#define MB_FULL(s)  (sb + 8  + (s) * 16)
#define MB_EMPTY(s) (sb + 16 + (s) * 16)
#define MB_DONE     (sb + 72)
#define MB_EPI      (sb + 80)

__global__ __launch_bounds__(256)
#if HAS_TCGEN05
__cluster_dims__(2, 1, 1)
#endif
void gemm_tc_kernel(const __grid_constant__ CUtensorMap tmA,
                    const __grid_constant__ CUtensorMap tmB,
                    const float* __restrict__ be, float* __restrict__ out,
                    int nTiles)
{
#if HAS_TCGEN05
    extern __shared__ char smem[];
    uint32_t sb = smem_u32(smem);
    const int tid  = threadIdx.x;
    const int wid  = tid >> 5;
    const int lane = tid & 31;
    uint32_t rank;
    asm("mov.u32 %0, %%cluster_ctarank;" : "=r"(rank));
    const int clusterId = blockIdx.x >> 1;

    float* sBias = (float*)(smem + 128);    // 512 f32
    float* sBp   = (float*)(smem + 2176);   // 128 f32
    int*   sTo   = (int*)  (smem + 2688);   // 128 i32
    const uint32_t buf0 = sb + 4096;

    if (wid == 0) TCGEN05_ALLOC_CG2(sb + 0, 512);
    if (tid == 0) {
        #pragma unroll
        for (int s = 0; s < NSTAGES; ++s) {
            MBARRIER_INIT(MB_FULL(s), 1);
            MBARRIER_INIT(MB_EMPTY(s), 1);
        }
        MBARRIER_INIT(MB_DONE, 1);
        MBARRIER_INIT(MB_EPI, 2);
    }
    __syncthreads();
    CLUSTER_SYNC();
    uint32_t tmem;
    asm volatile("ld.shared.b32 %0, [%1];" : "=r"(tmem) : "r"(sb + 0));

    const int NST = H_DIM / GBK;   // 16

    int phE[NSTAGES] = {1, 1, 1, 1};
    int phF[NSTAGES] = {0, 0, 0, 0};
    int slotP = 0, slotC = 0;
    int donePh = 0, epiPh = 0;
    int firstTile = 1;

    for (int ti = clusterId; ti < nTiles; ti += NCLUSTERS) {
        const int rowBase = (ti >> 1) * GBM;
        const int colBase = (ti & 1) * GBN;

        if (wid == 1 && elect_one_pred()) {
            for (int kt = 0; kt < NST; ++kt) {
                const int s = slotP;
                MBARRIER_WAIT_PARITY(MB_EMPTY(s), phE[s]); phE[s] ^= 1;
                const uint32_t ab = buf0 + s * STAGE_BYTES;
                if (rank == 0) MBARRIER_EXPECT_TX(MB_FULL(s), 2 * STAGE_BYTES);
                TMA_LOAD_2D_CG2(ab,               &tmA, kt * GBK,
                                rowBase + (int)rank * 128, MB_FULL(s));
                TMA_LOAD_2D_CG2(ab + A_ST,        &tmB, kt * GBK,
                                colBase + (int)rank * 128, MB_FULL(s));
                TMA_LOAD_2D_CG2(ab + A_ST + B_ST, &tmB, kt * GBK,
                                colBase + 256 + (int)rank * 128, MB_FULL(s));
                slotP = (slotP + 1) & (NSTAGES - 1);
            }
        }
        if (rank == 0 && wid == 0 && elect_one_pred()) {
            if (!firstTile) { MBARRIER_WAIT_PARITY(MB_EPI, epiPh); epiPh ^= 1; }
            for (int kt = 0; kt < NST; ++kt) {
                const int s = slotC;
                MBARRIER_WAIT_PARITY(MB_FULL(s), phF[s]); phF[s] ^= 1;
                const uint32_t ab = buf0 + s * STAGE_BYTES;
                uint64_t ad  = MAKE_SMEM_DESC(ab);
                uint64_t bd0 = MAKE_SMEM_DESC(ab + A_ST);
                uint64_t bd1 = MAKE_SMEM_DESC(ab + A_ST + B_ST);
                #pragma unroll
                for (int ks = 0; ks < 4; ++ks) {   // 4 x K=16 per 64-K stage
                    uint32_t en = (kt | ks) != 0;
                    mma_f16_ss_cg2(tmem,       ad + ks * 2, bd0 + ks * 2, en);
                    mma_f16_ss_cg2(tmem + 256, ad + ks * 2, bd1 + ks * 2, en);
                }
                TCGEN05_COMMIT_MC_CG2(MB_EMPTY(s), 0x3);
                slotC = (slotC + 1) & (NSTAGES - 1);
            }
            TCGEN05_COMMIT_MC_CG2(MB_DONE, 0x3);
        }

        // per-tile epilogue staging
        sBias[tid]       = be[colBase + tid];
        sBias[tid + 256] = be[colBase + 256 + tid];
        if (tid < 128) {
            int srow = rowBase + (int)rank * 128 + tid;
            int trow = g_inv[srow];
            sTo[tid] = trow;
            sBp[tid] = g_bestp[trow];
        }

        MBARRIER_WAIT_PARITY(MB_DONE, donePh); donePh ^= 1;
        TCGEN05_FENCE_AFTER();
        __syncthreads();

        {
            const int sub    = wid & 3;
            const int half   = wid >> 2;
            const int rowLoc = sub * 32 + lane;
            const float p = sBp[rowLoc];
            const uint32_t dbase = tmem + half * 256;
            float* orow = out + (size_t)sTo[rowLoc] * H_DIM + colBase + half * 256;
            #pragma unroll
            for (int ch = 0; ch < 8; ++ch) {
                uint32_t r[32];
                TCGEN05_LD_32X32B_X32(r, dbase + ch * 32);
                TCGEN05_WAIT_LD();
                #pragma unroll
                for (int i = 0; i < 32; i += 4) {
                    const int c = half * 256 + ch * 32 + i;
                    float4 v;
                    v.x = (__uint_as_float(r[i + 0]) + sBias[c + 0]) * p;
                    v.y = (__uint_as_float(r[i + 1]) + sBias[c + 1]) * p;
                    v.z = (__uint_as_float(r[i + 2]) + sBias[c + 2]) * p;
                    v.w = (__uint_as_float(r[i + 3]) + sBias[c + 3]) * p;
                    *(float4*)(orow + ch * 32 + i) = v;
                }
            }
            TCGEN05_FENCE_BEFORE();
        }
        __syncthreads();
        if (tid == 0) MBARRIER_ARRIVE_LEADER(MB_EPI);
        firstTile = 0;
    }

    __syncthreads();
    CLUSTER_SYNC();
    if (tid == 0) {
        #pragma unroll
        for (int s = 0; s < NSTAGES; ++s) {
            MBARRIER_INVAL(MB_FULL(s));
            MBARRIER_INVAL(MB_EMPTY(s));
        }
        MBARRIER_INVAL(MB_DONE);
        MBARRIER_INVAL(MB_EPI);
    }
    __syncthreads();
    if (wid == 0) {
        TCGEN05_RELINQ_CG2();
        TCGEN05_DEALLOC_CG2(tmem, 512);
    }
    CLUSTER_SYNC();
#endif  // HAS_TCGEN05
}

// =====================================================================
// Kernel 6b: WMMA fp16 fallback 128x128 (ALL passes) — natural-order A,
// row-scatter epilogue via g_inv. m16n16k16 half.
// =====================================================================
#define FBM 128
#define FBN 128
#define FBK 16
#define FLD 32     // halves per padded row (64 B, keeps wmma alignment)
#define FNKT (H_DIM / FBK)
#define FB_SMEM ((2*FBM*FLD + 2*FBN*FLD) * 2 + (8*256 + FBN + FBM + FBM) * 4)

__global__ __launch_bounds__(256) void gemm_wmma_kernel(
    const float* __restrict__ be, float* __restrict__ out)
{
    extern __shared__ char fsmc[];
    __half* As   = (__half*)fsmc;
    __half* Bs   = As + 2 * FBM * FLD;
    float* sC    = (float*)(Bs + 2 * FBN * FLD);
    float* sBias = sC + 8 * 256;
    float* sBp   = sBias + FBN;
    int*   sTo   = (int*)(sBp + FBM);

    const int tid = threadIdx.x;
    const int rowBase = blockIdx.y * FBM;
    const int colBase = blockIdx.x * FBN;

    if (tid < FBM) {
        int trow = g_inv[rowBase + tid];
        sTo[tid] = trow;
        sBp[tid] = g_bestp[trow];
    } else {
        sBias[tid - FBM] = be[colBase + tid - FBM];
    }

    const int arow = tid >> 1;
    const int aseg = (tid & 1) * 8;          // halves
    const __half* aSrc = g_A  + (size_t)(rowBase + arow) * H_DIM + aseg;
    const __half* bSrc = g_Wt + (size_t)(colBase + arow) * H_DIM + aseg;
    const uint32_t asm_base = smem_u32(As);
    const uint32_t bsm_base = smem_u32(Bs);

    auto load_tiles = [&](int buf, int kt) {
        const int k0 = kt * FBK;
        uint32_t ao = asm_base + (buf * FBM * FLD + arow * FLD + aseg) * 2;
        uint32_t bo = bsm_base + (buf * FBN * FLD + arow * FLD + aseg) * 2;
        cp16(ao, aSrc + k0);                  // 8 halves = 16 B
        cp16(bo, bSrc + k0);
    };

    const int warpId = tid >> 5;
    const int wm = warpId >> 2;
    const int wn = warpId & 3;

    wmma::fragment<wmma::accumulator, 16, 16, 16, float> acc[4][2];
    #pragma unroll
    for (int mi = 0; mi < 4; ++mi)
        #pragma unroll
        for (int ni = 0; ni < 2; ++ni)
            wmma::fill_fragment(acc[mi][ni], 0.0f);

    load_tiles(0, 0);
    cp_commit();

    for (int kt = 0; kt < FNKT; ++kt) {
        if (kt + 1 < FNKT) {
            load_tiles((kt + 1) & 1, kt + 1);
            cp_commit();
            cp_wait<1>();
        } else {
            cp_wait<0>();
        }
        __syncthreads();

        const int buf = kt & 1;
        wmma::fragment<wmma::matrix_a, 16, 16, 16, __half, wmma::row_major> af[4];
        wmma::fragment<wmma::matrix_b, 16, 16, 16, __half, wmma::col_major> bf[2];
        #pragma unroll
        for (int mi = 0; mi < 4; ++mi)
            wmma::load_matrix_sync(
                af[mi], &As[buf * FBM * FLD + (wm * 64 + mi * 16) * FLD], FLD);
        #pragma unroll
        for (int ni = 0; ni < 2; ++ni)
            wmma::load_matrix_sync(
                bf[ni], &Bs[buf * FBN * FLD + (wn * 32 + ni * 16) * FLD], FLD);
        #pragma unroll
        for (int mi = 0; mi < 4; ++mi)
            #pragma unroll
            for (int ni = 0; ni < 2; ++ni)
                wmma::mma_sync(acc[mi][ni], af[mi], bf[ni], acc[mi][ni]);
        __syncthreads();
    }

    const int lane = tid & 31;
    float* stg = &sC[warpId * 256];
    #pragma unroll
    for (int mi = 0; mi < 4; ++mi) {
        #pragma unroll
        for (int ni = 0; ni < 2; ++ni) {
            wmma::store_matrix_sync(stg, acc[mi][ni], 16, wmma::mem_row_major);
            __syncwarp();
            const int r = lane >> 1;
            const int c = (lane & 1) * 8;
            const int rowL = wm * 64 + mi * 16 + r;
            const int colL = wn * 32 + ni * 16 + c;
            const float p = sBp[rowL];
            float4 v0 = *(const float4*)&stg[r * 16 + c];
            float4 v1 = *(const float4*)&stg[r * 16 + c + 4];
            float4 o0, o1;
            o0.x = (v0.x + sBias[colL + 0]) * p;
            o0.y = (v0.y + sBias[colL + 1]) * p;
            o0.z = (v0.z + sBias[colL + 2]) * p;
            o0.w = (v0.w + sBias[colL + 3]) * p;
            o1.x = (v1.x + sBias[colL + 4]) * p;
            o1.y = (v1.y + sBias[colL + 5]) * p;
            o1.z = (v1.z + sBias[colL + 6]) * p;
            o1.w = (v1.w + sBias[colL + 7]) * p;
            float* dst = out + (size_t)sTo[rowL] * H_DIM + colBase + colL;
            *(float4*)(dst + 0) = o0;
            *(float4*)(dst + 4) = o1;
            __syncwarp();
        }
    }
}

// =====================================================================
// host: tensor-map construction via driver entry point (no -lcuda link)
// =====================================================================
typedef CUresult (*PFN_encodeTiled)(
    CUtensorMap*, CUtensorMapDataType, cuuint32_t, void*,
    const cuuint64_t*, const cuuint64_t*, const cuuint32_t*, const cuuint32_t*,
    CUtensorMapInterleave, CUtensorMapSwizzle, CUtensorMapL2promotion,
    CUtensorMapFloatOOBfill);

static PFN_encodeTiled get_encode_fn()
{
    void* fn = nullptr;
    cudaDriverEntryPointQueryResult qres = cudaDriverEntryPointSymbolNotFound;
#if CUDART_VERSION >= 12050
    cudaGetDriverEntryPointByVersion("cuTensorMapEncodeTiled", &fn, 12000,
                                     cudaEnableDefault, &qres);
#else
    cudaGetDriverEntryPoint("cuTensorMapEncodeTiled", &fn,
                            cudaEnableDefault, &qres);
#endif
    if (qres != cudaDriverEntryPointSuccess) return nullptr;
    return (PFN_encodeTiled)fn;
}

static bool make_map_f16(PFN_encodeTiled enc, CUtensorMap* tm, void* base,
                         uint64_t d0, uint64_t d1, uint32_t b0, uint32_t b1)
{
    cuuint64_t dims[2]    = {d0, d1};
    cuuint64_t strides[1] = {d0 * 2};
    cuuint32_t box[2]     = {b0, b1};
    cuuint32_t es[2]      = {1, 1};
    CUresult r = enc(tm, CU_TENSOR_MAP_DATA_TYPE_FLOAT16, 2, base,
                     dims, strides, box, es,
                     CU_TENSOR_MAP_INTERLEAVE_NONE, CU_TENSOR_MAP_SWIZZLE_128B,
                     CU_TENSOR_MAP_L2_PROMOTION_L2_128B,
                     CU_TENSOR_MAP_FLOAT_OOB_FILL_NONE);
    return r == CUDA_SUCCESS;
}

// =====================================================================
// launch
// =====================================================================
extern "C" void kernel_launch(void* const* d_in, const int* in_sizes, int n_in,
                              void* d_out, int out_size)
{
    const float* x  = (const float*)d_in[0];
    const float* Wr = (const float*)d_in[1];
    const float* br = (const float*)d_in[2];
    const float* We = (const float*)d_in[3];
    const float* be = (const float*)d_in[4];
    float* out = (float*)d_out;

    const int T  = in_sizes[0] / H_DIM;   // 32768
    const int NB = T / 256;

    router_kernel<<<T / 32, 256>>>(x, Wr, br, T);
    transpose_round_kernel<<<dim3(H_DIM / 32, H_DIM / 32), dim3(32, 32)>>>(We);
    hist_kernel<<<NB, 256>>>(T);
    offsets_kernel<<<1, 256>>>(NB);
    scatter_kernel<<<NB, 256>>>(T);

    cudaFuncAttributes attr;
    attr.numRegs = 0;
    cudaFuncGetAttributes(&attr, (const void*)gemm_tc_kernel);

    bool tc_ok = (attr.numRegs > 32);
    CUtensorMap tmA, tmB;
    if (tc_ok) {
        PFN_encodeTiled enc = get_encode_fn();
        void *pA = nullptr, *pW = nullptr;
        tc_ok = enc != nullptr
             && cudaGetSymbolAddress(&pA, g_A)  == cudaSuccess
             && cudaGetSymbolAddress(&pW, g_Wt) == cudaSuccess
             && make_map_f16(enc, &tmA, pA, H_DIM, (uint64_t)T, GBK, 128)
             && make_map_f16(enc, &tmB, pW, H_DIM, H_DIM,       GBK, 128);
    }

    if (tc_ok) {
        cudaFuncSetAttribute(gemm_tc_kernel,
                             cudaFuncAttributeMaxDynamicSharedMemorySize, GEMM_SMEM);
        const int nTiles = (T / GBM) * (H_DIM / GBN);   // 256
        gemm_tc_kernel<<<GEMM_GRID, 256, GEMM_SMEM>>>(tmA, tmB, be, out, nTiles);
    } else {
        cudaFuncSetAttribute(gemm_wmma_kernel,
                             cudaFuncAttributeMaxDynamicSharedMemorySize, FB_SMEM);
        dim3 gfb(H_DIM / FBN, T / FBM);   // (8, 256)
        gemm_wmma_kernel<<<gfb, 256, FB_SMEM>>>(be, out);
    }
}

// round 12
// speedup vs baseline: 1.4347x; 1.0020x over previous
#include <cuda_runtime.h>
#include <cuda_fp16.h>
#include <mma.h>
#include <cstdint>

using namespace nvcuda;

#define T_MAX 32768
#define H_DIM 1024
#define E_DIM 8

// tcgen05 is only legal in arch-accelerated (sm_10xa) compilation passes.
#if defined(__CUDA_ARCH_FEAT_SM103_ALL) || defined(__CUDA_ARCH_FEAT_SM100_ALL) || defined(__CUDA_ARCH_FEAT_SM101_ALL)
#define HAS_TCGEN05 1
#else
#define HAS_TCGEN05 0
#endif

// ---------------- scratch (no runtime allocations allowed) ----------------
__device__ int   g_best [T_MAX];
__device__ float g_bestp[T_MAX];
__device__ int   g_order[T_MAX];
__device__ int   g_inv  [T_MAX];
#define NB_MAX (T_MAX / 256)
__device__ int g_hist[NB_MAX * E_DIM];
__device__ int g_boff[NB_MAX * E_DIM];
// A and Wt stored as pre-swizzled 16KB tile images:
//   g_A : [T/128][16 kchunks][8192 halves]  (image = 128 rows x 128B, SW128)
//   g_Wt: [H/128][16 kchunks][8192 halves]
__device__ __half g_A [T_MAX * H_DIM];
__device__ __half g_Wt[H_DIM * H_DIM];

#define SWZ(o) ((o) ^ (((o) >> 3) & 0x70))

// ---------------- generic helpers ----------------
__device__ __forceinline__ uint32_t smem_u32(const void* p) {
    uint32_t a;
    asm("{ .reg .u64 t; cvta.to.shared.u64 t, %1; cvt.u32.u64 %0, t; }" : "=r"(a) : "l"(p));
    return a;
}
__device__ __forceinline__ void cp16(uint32_t saddr, const void* g) {
    asm volatile("cp.async.cg.shared.global [%0], [%1], 16;\n" :: "r"(saddr), "l"(g));
}
__device__ __forceinline__ void cp_commit() { asm volatile("cp.async.commit_group;\n"); }
template <int N> __device__ __forceinline__ void cp_wait() {
    asm volatile("cp.async.wait_group %0;\n" :: "n"(N));
}
__device__ __forceinline__ uint32_t elect_one_pred() {
    uint32_t pred;
    asm volatile(
        "{\n\t.reg .pred p;\n\t"
        "elect.sync _|p, 0xFFFFFFFF;\n\t"
        "selp.b32 %0, 1, 0, p;\n\t}"
        : "=r"(pred));
    return pred;
}

// =====================================================================
// Kernel 1: router — logits math UNCHANGED (defines the permutation);
// stores RN-fp16 x into the pre-swizzled tile-image layout of g_A.
// =====================================================================
__global__ __launch_bounds__(256) void router_kernel(
    const float* __restrict__ x, const float* __restrict__ Wr,
    const float* __restrict__ br, int T)
{
    __shared__ float sW[E_DIM][H_DIM];
    for (int i = threadIdx.x; i < H_DIM * E_DIM; i += 256) {
        int h = i >> 3, e = i & 7;
        sW[e][h] = Wr[i];
    }
    __syncthreads();

    int warp = threadIdx.x >> 5;
    int lane = threadIdx.x & 31;
    int tokBase = blockIdx.x * 32 + warp * 4;

    for (int tt = 0; tt < 4; ++tt) {
        int t = tokBase + tt;
        if (t >= T) break;
        const float* xr = x + (size_t)t * H_DIM;
        const int    r  = t & 127;
        __half* img = g_A + ((size_t)(t >> 7) * 16) * 8192;

        float acc[E_DIM];
        #pragma unroll
        for (int e = 0; e < E_DIM; ++e) acc[e] = 0.f;
        #pragma unroll 4
        for (int i = 0; i < H_DIM / 32; ++i) {
            float xv = xr[i * 32 + lane];
            // image store: kchunk = i>>1, byte off within 128B row
            int off = r * 128 + (i & 1) * 64 + lane * 2;
            img[(i >> 1) * 8192 + (SWZ(off) >> 1)] = __float2half_rn(xv);
            #pragma unroll
            for (int e = 0; e < E_DIM; ++e) acc[e] += xv * sW[e][i * 32 + lane];
        }
        #pragma unroll
        for (int e = 0; e < E_DIM; ++e) {
            #pragma unroll
            for (int off = 16; off; off >>= 1)
                acc[e] += __shfl_down_sync(0xffffffffu, acc[e], off);
        }
        if (lane == 0) {
            float l[E_DIM];
            #pragma unroll
            for (int e = 0; e < E_DIM; ++e) l[e] = acc[e] + br[e];
            int bi = 0; float bm = l[0];
            #pragma unroll
            for (int e = 1; e < E_DIM; ++e)
                if (l[e] > bm) { bm = l[e]; bi = e; }
            float s = 0.f;
            #pragma unroll
            for (int e = 0; e < E_DIM; ++e) s += expf(l[e] - bm);
            g_best [t] = bi;
            g_bestp[t] = 1.0f / s;
        }
    }
}

// =====================================================================
// Kernels 2-4: stable counting sort (unchanged)
// =====================================================================
__global__ void hist_kernel(int T)
{
    __shared__ int sh[E_DIM];
    if (threadIdx.x < E_DIM) sh[threadIdx.x] = 0;
    __syncthreads();
    int t = blockIdx.x * 256 + threadIdx.x;
    if (t < T) atomicAdd(&sh[g_best[t]], 1);
    __syncthreads();
    if (threadIdx.x < E_DIM)
        g_hist[blockIdx.x * E_DIM + threadIdx.x] = sh[threadIdx.x];
}

__global__ __launch_bounds__(256) void offsets_kernel(int NB)
{
    __shared__ int sh[NB_MAX * E_DIM];
    __shared__ int tot[E_DIM];
    __shared__ int base[E_DIM];
    const int tid = threadIdx.x;
    for (int i = tid; i < NB * E_DIM; i += 256) sh[i] = g_hist[i];
    __syncthreads();

    const int w = tid >> 5, l = tid & 31;
    if (w < E_DIM) {
        int run = 0;
        for (int c = 0; c < NB; c += 32) {
            int v = sh[(c + l) * E_DIM + w];
            int xs = v;
            #pragma unroll
            for (int off = 1; off < 32; off <<= 1) {
                int y = __shfl_up_sync(0xffffffffu, xs, off);
                if (l >= off) xs += y;
            }
            sh[(c + l) * E_DIM + w] = xs - v + run;
            run += __shfl_sync(0xffffffffu, xs, 31);
        }
        if (l == 0) tot[w] = run;
    }
    __syncthreads();
    if (tid == 0) {
        int b = 0;
        #pragma unroll
        for (int e = 0; e < E_DIM; ++e) { base[e] = b; b += tot[e]; }
    }
    __syncthreads();
    for (int i = tid; i < NB * E_DIM; i += 256)
        g_boff[i] = sh[i] + base[i & (E_DIM - 1)];
}

__global__ void scatter_kernel(int T)
{
    __shared__ int sb[256];
    int i = threadIdx.x;
    int t = blockIdx.x * 256 + i;
    sb[i] = (t < T) ? g_best[t] : -1;
    __syncthreads();
    if (t < T) {
        int e = sb[i];
        int rank = 0;
        for (int j = 0; j < i; ++j) rank += (sb[j] == e);
        int pos = g_boff[blockIdx.x * E_DIM + e] + rank;
        g_order[pos] = t;
        g_inv[t]     = pos;
    }
}

// =====================================================================
// Kernel 5: transpose W_expert -> pre-swizzled [N,K] tile images
// =====================================================================
__global__ void transpose_round_kernel(const float* __restrict__ We)
{
    __shared__ float tile[32][33];
    int n = blockIdx.x * 32 + threadIdx.x;
    int k = blockIdx.y * 32 + threadIdx.y;
    tile[threadIdx.y][threadIdx.x] = We[(size_t)k * H_DIM + n];
    __syncthreads();
    int on = blockIdx.x * 32 + threadIdx.y;   // N index
    int ok = blockIdx.y * 32 + threadIdx.x;   // K index
    int off = (on & 127) * 128 + (ok & 63) * 2;
    g_Wt[((size_t)((on >> 7) * 16 + (ok >> 6))) * 8192 + (SWZ(off) >> 1)] =
        __float2half_rn(tile[threadIdx.x][threadIdx.y]);
}

// =====================================================================
// tcgen05-only machinery
// =====================================================================
#if HAS_TCGEN05

#define MBARRIER_INIT(addr, cnt) \
    asm volatile("mbarrier.init.shared.b64 [%0], %1;" :: "r"((uint32_t)(addr)), "r"((uint32_t)(cnt)) : "memory")
#define MBARRIER_INVAL(addr) \
    asm volatile("mbarrier.inval.shared.b64 [%0];" :: "r"((uint32_t)(addr)) : "memory")
#define MBARRIER_EXPECT_TX(addr, bytes) \
    asm volatile("mbarrier.arrive.expect_tx.shared.b64 _, [%0], %1;" \
                 :: "r"((uint32_t)(addr)), "r"((uint32_t)(bytes)) : "memory")
#define MBARRIER_WAIT_PARITY(mbar, parity) do {                                   \
    asm volatile(                                                                 \
        "{\n\t.reg .pred P1;\n\t"                                                 \
        "WAIT_LOOP_%=:\n\t"                                                       \
        "mbarrier.try_wait.parity.acquire.cta.shared::cta.b64 P1, [%0], %1, 0x989680;\n\t" \
        "@P1 bra.uni WAIT_DONE_%=;\n\t"                                           \
        "bra.uni WAIT_LOOP_%=;\n\t"                                               \
        "WAIT_DONE_%=:\n\t}"                                                      \
        :: "r"((uint32_t)(mbar)), "r"((uint32_t)(parity)) : "memory");            \
} while (0)

// arrive on the PAIR LEADER's mbarrier (clear bit 24 = Sm100MmaPeerBitMask)
#define MBARRIER_ARRIVE_LEADER(addr)                                      \
    asm volatile(                                                         \
        "{\n\t.reg .b32 lb;\n\t"                                          \
        "and.b32 lb, %0, 0xFEFFFFFF;\n\t"                                 \
        "mbarrier.arrive.shared::cluster.b64 _, [lb];\n\t}"               \
        :: "r"((uint32_t)(addr)) : "memory")

#define CLUSTER_SYNC() do {                                              \
    asm volatile("barrier.cluster.arrive.aligned;" ::: "memory");        \
    asm volatile("barrier.cluster.wait.aligned;" ::: "memory");          \
} while (0)

// plain bulk copy global->shared, 16B granularity, completes on [mbar]
#define BULK_CP(dst, src, bytes, mbar)                                    \
    asm volatile(                                                         \
        "cp.async.bulk.shared::cluster.global.mbarrier::complete_tx::bytes " \
        "[%0], [%1], %2, [%3];"                                           \
        :: "r"((uint32_t)(dst)), "l"(src), "r"((uint32_t)(bytes)),        \
           "r"((uint32_t)(mbar)) : "memory")

#define TCGEN05_ALLOC_CG2(sres, n) \
    asm volatile("tcgen05.alloc.cta_group::2.sync.aligned.shared::cta.b32 [%0], %1;" \
                 :: "r"((uint32_t)(sres)), "r"((uint32_t)(n)) : "memory")
#define TCGEN05_DEALLOC_CG2(tm, n) \
    asm volatile("tcgen05.dealloc.cta_group::2.sync.aligned.b32 %0, %1;" :: "r"(tm), "r"((uint32_t)(n)))
#define TCGEN05_RELINQ_CG2() \
    asm volatile("tcgen05.relinquish_alloc_permit.cta_group::2.sync.aligned;")
#define TCGEN05_COMMIT_MC_CG2(mbar, mask) \
    asm volatile("tcgen05.commit.cta_group::2.mbarrier::arrive::one.shared::cluster.multicast::cluster.b64 [%0], %1;" \
                 :: "r"((uint32_t)(mbar)), "h"((uint16_t)(mask)) : "memory")
#define TCGEN05_FENCE_AFTER()  asm volatile("tcgen05.fence::after_thread_sync;" ::: "memory")
#define TCGEN05_FENCE_BEFORE() asm volatile("tcgen05.fence::before_thread_sync;" ::: "memory")
#define TCGEN05_WAIT_LD()      asm volatile("tcgen05.wait::ld.sync.aligned;" ::: "memory")

#define TCGEN05_LD_32X32B_X32(r, tmem_addr)                                     \
    asm volatile(                                                               \
        "tcgen05.ld.sync.aligned.32x32b.x32.b32 "                               \
        "{%0, %1, %2, %3, %4, %5, %6, %7, "                                     \
        " %8, %9, %10, %11, %12, %13, %14, %15, "                               \
        " %16, %17, %18, %19, %20, %21, %22, %23, "                             \
        " %24, %25, %26, %27, %28, %29, %30, %31}, [%32];"                      \
        : "=r"((r)[0]),  "=r"((r)[1]),  "=r"((r)[2]),  "=r"((r)[3]),            \
          "=r"((r)[4]),  "=r"((r)[5]),  "=r"((r)[6]),  "=r"((r)[7]),            \
          "=r"((r)[8]),  "=r"((r)[9]),  "=r"((r)[10]), "=r"((r)[11]),           \
          "=r"((r)[12]), "=r"((r)[13]), "=r"((r)[14]), "=r"((r)[15]),           \
          "=r"((r)[16]), "=r"((r)[17]), "=r"((r)[18]), "=r"((r)[19]),           \
          "=r"((r)[20]), "=r"((r)[21]), "=r"((r)[22]), "=r"((r)[23]),           \
          "=r"((r)[24]), "=r"((r)[25]), "=r"((r)[26]), "=r"((r)[27]),           \
          "=r"((r)[28]), "=r"((r)[29]), "=r"((r)[30]), "=r"((r)[31])            \
        : "r"(tmem_addr))

static constexpr uint64_t SMEM_DESC_BASE_SW128 =
    (uint64_t(2)  << 61) | (uint64_t(1) << 46) | (uint64_t(64) << 32) | (uint64_t(1) << 16);
#define MAKE_SMEM_DESC(base) (SMEM_DESC_BASE_SW128 | ((uint64_t)((base) >> 4) & 0x3FFF))

// idesc kind::f16, cg2: d=F32(1<<4), fp16 a/b, N=256, M=256 -> 0x10400010
#define GEMM_IDESC_F16_CG2 0x10400010u

__device__ __forceinline__ void mma_f16_ss_cg2(uint32_t d, uint64_t a, uint64_t b, uint32_t en) {
    asm volatile(
        "{\n\t.reg .pred p;\n\t"
        "setp.ne.u32 p, %4, 0;\n\t"
        "tcgen05.mma.cta_group::2.kind::f16 [%0], %1, %2, %3, "
        "{%5, %5, %5, %5, %5, %5, %5, %5}, p;\n\t}"
        :: "r"(d), "l"(a), "l"(b), "r"(GEMM_IDESC_F16_CG2), "r"(en), "r"(0u) : "memory");
}
#endif  // HAS_TCGEN05

// =====================================================================
// Kernel 6a: PERSISTENT fp16 cg2 pair-GEMM, bulk-copy tile images.
// Per stage/CTA: 3 x 16KB cp.async.bulk (1 op each, no TMA row-gen).
// rank0 copies -> leader full[s] (expect_tx); rank1 copies -> local
// fullR[s]; a rank1 relay warp forwards completion to leader full[s].
// =====================================================================
#define GBM 256
#define GBN 512
#define GBK 64
#define A_ST 16384
#define B_ST 16384
#define STAGE_BYTES (A_ST + 2 * B_ST)   // 49152 B
#define NSTAGES 4
#define GEMM_SMEM (4096 + NSTAGES * STAGE_BYTES)   // 200704 B
#define NCLUSTERS 74
#define GEMM_GRID  (2 * NCLUSTERS)

// ctrl: 0 tmem ptr; full(s)=8+16s; empty(s)=16+16s; done=72; epi=80; fullR(s)=88+8s
#define MB_FULL(s)  (sb + 8  + (s) * 16)
#define MB_EMPTY(s) (sb + 16 + (s) * 16)
#define MB_DONE     (sb + 72)
#define MB_EPI      (sb + 80)
#define MB_FULLR(s) (sb + 88 + (s) * 8)

__global__ __launch_bounds__(256)
#if HAS_TCGEN05
__cluster_dims__(2, 1, 1)
#endif
void gemm_tc_kernel(const float* __restrict__ be, float* __restrict__ out,
                    int nTiles)
{
#if HAS_TCGEN05
    extern __shared__ char smem[];
    uint32_t sb = smem_u32(smem);
    const int tid  = threadIdx.x;
    const int wid  = tid >> 5;
    const int lane = tid & 31;
    uint32_t rank;
    asm("mov.u32 %0, %%cluster_ctarank;" : "=r"(rank));
    const int clusterId = blockIdx.x >> 1;

    float* sBias = (float*)(smem + 256);    // 512 f32 -> [256, 2304)
    float* sBp   = (float*)(smem + 2304);   // 128 f32 -> [2304, 2816)
    int*   sTo   = (int*)  (smem + 2816);   // 128 i32 -> [2816, 3328)
    const uint32_t buf0 = sb + 4096;

    if (wid == 0) TCGEN05_ALLOC_CG2(sb + 0, 512);
    if (tid == 0) {
        #pragma unroll
        for (int s = 0; s < NSTAGES; ++s) {
            MBARRIER_INIT(MB_FULL(s), 2);    // expect_tx arrive + relay arrive
            MBARRIER_INIT(MB_EMPTY(s), 1);
            MBARRIER_INIT(MB_FULLR(s), 1);
        }
        MBARRIER_INIT(MB_DONE, 1);
        MBARRIER_INIT(MB_EPI, 2);
    }
    __syncthreads();
    CLUSTER_SYNC();
    uint32_t tmem;
    asm volatile("ld.shared.b32 %0, [%1];" : "=r"(tmem) : "r"(sb + 0));

    const int NST = H_DIM / GBK;   // 16

    int phE[NSTAGES] = {1, 1, 1, 1};   // producer empty-waits
    int phF[NSTAGES] = {0, 0, 0, 0};   // leader full-waits
    int phR[NSTAGES] = {0, 0, 0, 0};   // relay fullR-waits
    int slotP = 0, slotC = 0, slotR = 0;
    int donePh = 0, epiPh = 0;
    int firstTile = 1;

    for (int ti = clusterId; ti < nTiles; ti += NCLUSTERS) {
        const int rowBase = (ti >> 1) * GBM;
        const int colBase = (ti & 1) * GBN;
        // tile-image base pointers (halves); 8192 halves per 16KB image
        const __half* Abase  = g_A  + ((size_t)(((ti >> 1) * 2 + (int)rank) * 16)) * 8192;
        const __half* B0base = g_Wt + ((size_t)(((ti & 1) * 4 + (int)rank) * 16)) * 8192;
        const __half* B1base = g_Wt + ((size_t)(((ti & 1) * 4 + 2 + (int)rank) * 16)) * 8192;

        if (wid == 1 && elect_one_pred()) {
            // ---- producer: 3 x 16KB bulk copies per stage ----
            for (int kt = 0; kt < NST; ++kt) {
                const int s = slotP;
                MBARRIER_WAIT_PARITY(MB_EMPTY(s), phE[s]); phE[s] ^= 1;
                const uint32_t ab = buf0 + s * STAGE_BYTES;
                const uint32_t mbar = (rank == 0) ? MB_FULL(s) : MB_FULLR(s);
                MBARRIER_EXPECT_TX(mbar, STAGE_BYTES);
                BULK_CP(ab,               Abase  + (size_t)kt * 8192, A_ST, mbar);
                BULK_CP(ab + A_ST,        B0base + (size_t)kt * 8192, B_ST, mbar);
                BULK_CP(ab + A_ST + B_ST, B1base + (size_t)kt * 8192, B_ST, mbar);
                slotP = (slotP + 1) & (NSTAGES - 1);
            }
        }
        if (rank == 1 && wid == 2 && elect_one_pred()) {
            // ---- relay: forward rank1 stage completion to leader ----
            for (int kt = 0; kt < NST; ++kt) {
                const int s = slotR;
                MBARRIER_WAIT_PARITY(MB_FULLR(s), phR[s]); phR[s] ^= 1;
                MBARRIER_ARRIVE_LEADER(MB_FULL(s));
                slotR = (slotR + 1) & (NSTAGES - 1);
            }
        }
        if (rank == 0 && wid == 0 && elect_one_pred()) {
            // ---- leader MMA ----
            if (!firstTile) { MBARRIER_WAIT_PARITY(MB_EPI, epiPh); epiPh ^= 1; }
            for (int kt = 0; kt < NST; ++kt) {
                const int s = slotC;
                MBARRIER_WAIT_PARITY(MB_FULL(s), phF[s]); phF[s] ^= 1;
                const uint32_t ab = buf0 + s * STAGE_BYTES;
                uint64_t ad  = MAKE_SMEM_DESC(ab);
                uint64_t bd0 = MAKE_SMEM_DESC(ab + A_ST);
                uint64_t bd1 = MAKE_SMEM_DESC(ab + A_ST + B_ST);
                #pragma unroll
                for (int ks = 0; ks < 4; ++ks) {   // 4 x K=16 per 64-K stage
                    uint32_t en = (kt | ks) != 0;
                    mma_f16_ss_cg2(tmem,       ad + ks * 2, bd0 + ks * 2, en);
                    mma_f16_ss_cg2(tmem + 256, ad + ks * 2, bd1 + ks * 2, en);
                }
                TCGEN05_COMMIT_MC_CG2(MB_EMPTY(s), 0x3);
                slotC = (slotC + 1) & (NSTAGES - 1);
            }
            TCGEN05_COMMIT_MC_CG2(MB_DONE, 0x3);
        }

        // per-tile epilogue staging
        sBias[tid]       = be[colBase + tid];
        sBias[tid + 256] = be[colBase + 256 + tid];
        if (tid < 128) {
            int srow = rowBase + (int)rank * 128 + tid;
            int trow = g_inv[srow];
            sTo[tid] = trow;
            sBp[tid] = g_bestp[trow];
        }

        MBARRIER_WAIT_PARITY(MB_DONE, donePh); donePh ^= 1;
        TCGEN05_FENCE_AFTER();
        __syncthreads();

        {
            const int sub    = wid & 3;
            const int half   = wid >> 2;
            const int rowLoc = sub * 32 + lane;
            const float p = sBp[rowLoc];
            const uint32_t dbase = tmem + half * 256;
            float* orow = out + (size_t)sTo[rowLoc] * H_DIM + colBase + half * 256;
            #pragma unroll
            for (int ch = 0; ch < 8; ++ch) {
                uint32_t r[32];
                TCGEN05_LD_32X32B_X32(r, dbase + ch * 32);
                TCGEN05_WAIT_LD();
                #pragma unroll
                for (int i = 0; i < 32; i += 4) {
                    const int c = half * 256 + ch * 32 + i;
                    float4 v;
                    v.x = (__uint_as_float(r[i + 0]) + sBias[c + 0]) * p;
                    v.y = (__uint_as_float(r[i + 1]) + sBias[c + 1]) * p;
                    v.z = (__uint_as_float(r[i + 2]) + sBias[c + 2]) * p;
                    v.w = (__uint_as_float(r[i + 3]) + sBias[c + 3]) * p;
                    *(float4*)(orow + ch * 32 + i) = v;
                }
            }
            TCGEN05_FENCE_BEFORE();
        }
        __syncthreads();
        if (tid == 0) MBARRIER_ARRIVE_LEADER(MB_EPI);
        firstTile = 0;
    }

    __syncthreads();
    CLUSTER_SYNC();
    if (tid == 0) {
        #pragma unroll
        for (int s = 0; s < NSTAGES; ++s) {
            MBARRIER_INVAL(MB_FULL(s));
            MBARRIER_INVAL(MB_EMPTY(s));
            MBARRIER_INVAL(MB_FULLR(s));
        }
        MBARRIER_INVAL(MB_DONE);
        MBARRIER_INVAL(MB_EPI);
    }
    __syncthreads();
    if (wid == 0) {
        TCGEN05_RELINQ_CG2();
        TCGEN05_DEALLOC_CG2(tmem, 512);
    }
    CLUSTER_SYNC();
#endif  // HAS_TCGEN05
}

// =====================================================================
// Kernel 6b: WMMA fp16 fallback 128x128 (ALL passes) — reads the
// swizzled tile-image layout; row-scatter epilogue via g_inv.
// =====================================================================
#define FBM 128
#define FBN 128
#define FBK 16
#define FLD 32
#define FNKT (H_DIM / FBK)
#define FB_SMEM ((2*FBM*FLD + 2*FBN*FLD) * 2 + (8*256 + FBN + FBM + FBM) * 4)

__device__ __forceinline__ const char* img_addr16(const __half* base, int row, int kpos) {
    // address of the 16B group holding halves [kpos, kpos+8) of logical row
    int off = (row & 127) * 128 + (kpos & 63) * 2;
    return (const char*)base
         + (((size_t)(row >> 7) * 16 + (kpos >> 6)) << 14) + SWZ(off);
}

__global__ __launch_bounds__(256) void gemm_wmma_kernel(
    const float* __restrict__ be, float* __restrict__ out)
{
    extern __shared__ char fsmc[];
    __half* As   = (__half*)fsmc;
    __half* Bs   = As + 2 * FBM * FLD;
    float* sC    = (float*)(Bs + 2 * FBN * FLD);
    float* sBias = sC + 8 * 256;
    float* sBp   = sBias + FBN;
    int*   sTo   = (int*)(sBp + FBM);

    const int tid = threadIdx.x;
    const int rowBase = blockIdx.y * FBM;
    const int colBase = blockIdx.x * FBN;

    if (tid < FBM) {
        int trow = g_inv[rowBase + tid];
        sTo[tid] = trow;
        sBp[tid] = g_bestp[trow];
    } else {
        sBias[tid - FBM] = be[colBase + tid - FBM];
    }

    const int arow = tid >> 1;
    const int aseg = (tid & 1) * 8;
    const uint32_t asm_base = smem_u32(As);
    const uint32_t bsm_base = smem_u32(Bs);

    auto load_tiles = [&](int buf, int kt) {
        const int kpos = kt * FBK + aseg;
        uint32_t ao = asm_base + (buf * FBM * FLD + arow * FLD + aseg) * 2;
        uint32_t bo = bsm_base + (buf * FBN * FLD + arow * FLD + aseg) * 2;
        cp16(ao, img_addr16(g_A,  rowBase + arow, kpos));
        cp16(bo, img_addr16(g_Wt, colBase + arow, kpos));
    };

    const int warpId = tid >> 5;
    const int wm = warpId >> 2;
    const int wn = warpId & 3;

    wmma::fragment<wmma::accumulator, 16, 16, 16, float> acc[4][2];
    #pragma unroll
    for (int mi = 0; mi < 4; ++mi)
        #pragma unroll
        for (int ni = 0; ni < 2; ++ni)
            wmma::fill_fragment(acc[mi][ni], 0.0f);

    load_tiles(0, 0);
    cp_commit();

    for (int kt = 0; kt < FNKT; ++kt) {
        if (kt + 1 < FNKT) {
            load_tiles((kt + 1) & 1, kt + 1);
            cp_commit();
            cp_wait<1>();
        } else {
            cp_wait<0>();
        }
        __syncthreads();

        const int buf = kt & 1;
        wmma::fragment<wmma::matrix_a, 16, 16, 16, __half, wmma::row_major> af[4];
        wmma::fragment<wmma::matrix_b, 16, 16, 16, __half, wmma::col_major> bf[2];
        #pragma unroll
        for (int mi = 0; mi < 4; ++mi)
            wmma::load_matrix_sync(
                af[mi], &As[buf * FBM * FLD + (wm * 64 + mi * 16) * FLD], FLD);
        #pragma unroll
        for (int ni = 0; ni < 2; ++ni)
            wmma::load_matrix_sync(
                bf[ni], &Bs[buf * FBN * FLD + (wn * 32 + ni * 16) * FLD], FLD);
        #pragma unroll
        for (int mi = 0; mi < 4; ++mi)
            #pragma unroll
            for (int ni = 0; ni < 2; ++ni)
                wmma::mma_sync(acc[mi][ni], af[mi], bf[ni], acc[mi][ni]);
        __syncthreads();
    }

    const int lane = tid & 31;
    float* stg = &sC[warpId * 256];
    #pragma unroll
    for (int mi = 0; mi < 4; ++mi) {
        #pragma unroll
        for (int ni = 0; ni < 2; ++ni) {
            wmma::store_matrix_sync(stg, acc[mi][ni], 16, wmma::mem_row_major);
            __syncwarp();
            const int r = lane >> 1;
            const int c = (lane & 1) * 8;
            const int rowL = wm * 64 + mi * 16 + r;
            const int colL = wn * 32 + ni * 16 + c;
            const float p = sBp[rowL];
            float4 v0 = *(const float4*)&stg[r * 16 + c];
            float4 v1 = *(const float4*)&stg[r * 16 + c + 4];
            float4 o0, o1;
            o0.x = (v0.x + sBias[colL + 0]) * p;
            o0.y = (v0.y + sBias[colL + 1]) * p;
            o0.z = (v0.z + sBias[colL + 2]) * p;
            o0.w = (v0.w + sBias[colL + 3]) * p;
            o1.x = (v1.x + sBias[colL + 4]) * p;
            o1.y = (v1.y + sBias[colL + 5]) * p;
            o1.z = (v1.z + sBias[colL + 6]) * p;
            o1.w = (v1.w + sBias[colL + 7]) * p;
            float* dst = out + (size_t)sTo[rowL] * H_DIM + colBase + colL;
            *(float4*)(dst + 0) = o0;
            *(float4*)(dst + 4) = o1;
            __syncwarp();
        }
    }
}

// =====================================================================
// launch
// =====================================================================
extern "C" void kernel_launch(void* const* d_in, const int* in_sizes, int n_in,
                              void* d_out, int out_size)
{
    const float* x  = (const float*)d_in[0];
    const float* Wr = (const float*)d_in[1];
    const float* br = (const float*)d_in[2];
    const float* We = (const float*)d_in[3];
    const float* be = (const float*)d_in[4];
    float* out = (float*)d_out;

    const int T  = in_sizes[0] / H_DIM;   // 32768
    const int NB = T / 256;

    router_kernel<<<T / 32, 256>>>(x, Wr, br, T);
    transpose_round_kernel<<<dim3(H_DIM / 32, H_DIM / 32), dim3(32, 32)>>>(We);
    hist_kernel<<<NB, 256>>>(T);
    offsets_kernel<<<1, 256>>>(NB);
    scatter_kernel<<<NB, 256>>>(T);

    cudaFuncAttributes attr;
    attr.numRegs = 0;
    cudaFuncGetAttributes(&attr, (const void*)gemm_tc_kernel);

    if (attr.numRegs > 32) {
        cudaFuncSetAttribute(gemm_tc_kernel,
                             cudaFuncAttributeMaxDynamicSharedMemorySize, GEMM_SMEM);
        const int nTiles = (T / GBM) * (H_DIM / GBN);   // 256
        gemm_tc_kernel<<<GEMM_GRID, 256, GEMM_SMEM>>>(be, out, nTiles);
    } else {
        cudaFuncSetAttribute(gemm_wmma_kernel,
                             cudaFuncAttributeMaxDynamicSharedMemorySize, FB_SMEM);
        dim3 gfb(H_DIM / FBN, T / FBM);   // (8, 256)
        gemm_wmma_kernel<<<gfb, 256, FB_SMEM>>>(be, out);
    }
}